// round 1
// baseline (speedup 1.0000x reference)
#include <cuda_runtime.h>
#include <math.h>

// Problem shape (fixed): N=8192, D_IN=1024, D_HID=4096, D_OUT=1024
#define NROWS 8192
#define DIN   1024
#define DHID  4096
#define DOUT  1024

// Scratch (allocation-free rule: __device__ globals). 128 MB each.
__device__ float g_buf0[NROWS * DHID];
__device__ float g_buf1[NROWS * DHID];

__device__ __forceinline__ float block_reduce_sum(float v) {
    __shared__ float sh[33];
    int lane = threadIdx.x & 31;
    int wid  = threadIdx.x >> 5;
    #pragma unroll
    for (int o = 16; o > 0; o >>= 1) v += __shfl_down_sync(0xffffffffu, v, o);
    if (lane == 0) sh[wid] = v;
    __syncthreads();
    if (wid == 0) {
        float t = (lane < (int)(blockDim.x >> 5)) ? sh[lane] : 0.0f;
        #pragma unroll
        for (int o = 16; o > 0; o >>= 1) t += __shfl_down_sync(0xffffffffu, t, o);
        if (lane == 0) sh[32] = t;
    }
    __syncthreads();
    return sh[32];
}

// Layer-1 prologue: t = logmap0(x_hyp). t[:,0]=0, t[:,j]=acosh(x0)/||xs|| * x[:,j]
// One block per row, 256 threads, D=1024 -> one float4 per thread.
__global__ __launch_bounds__(256) void prep_kernel(const float* __restrict__ x,
                                                   float* __restrict__ o) {
    int row = blockIdx.x;
    const float4* xr = reinterpret_cast<const float4*>(x + (size_t)row * DIN);
    float4* orow = reinterpret_cast<float4*>(o + (size_t)row * DIN);
    float4 v = xr[threadIdx.x];
    float ss;
    __shared__ float s_x0;
    if (threadIdx.x == 0) {
        s_x0 = v.x;
        ss = v.y * v.y + v.z * v.z + v.w * v.w;
    } else {
        ss = v.x * v.x + v.y * v.y + v.z * v.z + v.w * v.w;
    }
    float tot = block_reduce_sum(ss);
    float ns = fmaxf(sqrtf(tot), 1e-7f);
    float d = acoshf(fmaxf(s_x0, 1.0f + 1e-7f));
    float s = d / ns;
    float4 w;
    w.x = v.x * s; w.y = v.y * s; w.z = v.z * s; w.w = v.w * s;
    if (threadIdx.x == 0) w.x = 0.0f;
    orow[threadIdx.x] = w;
}

// Inter-layer fused nonlinearity: given y (N x D), next GEMM input is
// [0, min(||y[:,1:]||,10)/||y[:,1:]|| * y[:,1:]]  (all hyperbolic maps cancel)
__global__ __launch_bounds__(256) void transform_kernel(const float* __restrict__ y,
                                                        float* __restrict__ o, int D) {
    int row = blockIdx.x;
    const float4* yr = reinterpret_cast<const float4*>(y + (size_t)row * D);
    float4* orow = reinterpret_cast<float4*>(o + (size_t)row * D);
    int n4 = D >> 2;
    float ss = 0.0f;
    for (int i = threadIdx.x; i < n4; i += blockDim.x) {
        float4 v = yr[i];
        if (i == 0) ss += v.y * v.y + v.z * v.z + v.w * v.w;
        else        ss += v.x * v.x + v.y * v.y + v.z * v.z + v.w * v.w;
    }
    float n = fmaxf(sqrtf(block_reduce_sum(ss)), 1e-7f);
    float f = fminf(n, 10.0f) / n;
    for (int i = threadIdx.x; i < n4; i += blockDim.x) {
        float4 v = yr[i];
        float4 w;
        w.x = v.x * f; w.y = v.y * f; w.z = v.z * f; w.w = v.w * f;
        if (i == 0) w.x = 0.0f;
        orow[i] = w;
    }
}

// Final epilogue: out = [cosh(nc), sinh(nc)/n * y[:,1:]], nc = min(n,10)
__global__ __launch_bounds__(256) void final_kernel(const float* __restrict__ y,
                                                    float* __restrict__ o) {
    int row = blockIdx.x;
    const float4* yr = reinterpret_cast<const float4*>(y + (size_t)row * DOUT);
    float4* orow = reinterpret_cast<float4*>(o + (size_t)row * DOUT);
    float4 v = yr[threadIdx.x];
    float ss;
    if (threadIdx.x == 0) ss = v.y * v.y + v.z * v.z + v.w * v.w;
    else                  ss = v.x * v.x + v.y * v.y + v.z * v.z + v.w * v.w;
    float n = fmaxf(sqrtf(block_reduce_sum(ss)), 1e-7f);
    float nc = fminf(n, 10.0f);
    float f = sinhf(nc) / n;
    float4 w;
    w.x = v.x * f; w.y = v.y * f; w.z = v.z * f; w.w = v.w * f;
    if (threadIdx.x == 0) w.x = coshf(nc);
    orow[threadIdx.x] = w;
}

// C[M,N] = A[M,K] * B[N,K]^T + bias[N]   (both row-major, K inner: TN GEMM)
// Tile 128x128x16, 256 threads, 8x8 per thread.
__global__ __launch_bounds__(256) void gemm_tn_bias(const float* __restrict__ A,
                                                    const float* __restrict__ B,
                                                    const float* __restrict__ bias,
                                                    float* __restrict__ C,
                                                    int M, int N, int K) {
    const int BM = 128, BN = 128, BK = 16, TM = 8, TN = 8;
    __shared__ float As[BK][BM];
    __shared__ float Bs[BK][BN];
    const int bm = blockIdx.y * BM;
    const int bn = blockIdx.x * BN;
    const int tid = threadIdx.x;
    const int tx = tid & 15;   // N-dim
    const int ty = tid >> 4;   // M-dim

    float acc[TM][TN];
    #pragma unroll
    for (int i = 0; i < TM; i++)
        #pragma unroll
        for (int j = 0; j < TN; j++) acc[i][j] = 0.0f;

    for (int k0 = 0; k0 < K; k0 += BK) {
        // Load A tile (128x16) as float4, store transposed [k][m]
        #pragma unroll
        for (int it = 0; it < 2; ++it) {
            int idx = tid + it * 256;        // 0..511 float4 slots
            int row = idx >> 2;
            int c4  = (idx & 3) << 2;
            float4 v = *reinterpret_cast<const float4*>(&A[(size_t)(bm + row) * K + k0 + c4]);
            As[c4 + 0][row] = v.x;
            As[c4 + 1][row] = v.y;
            As[c4 + 2][row] = v.z;
            As[c4 + 3][row] = v.w;
        }
        // Load B tile (128x16)
        #pragma unroll
        for (int it = 0; it < 2; ++it) {
            int idx = tid + it * 256;
            int row = idx >> 2;
            int c4  = (idx & 3) << 2;
            float4 v = *reinterpret_cast<const float4*>(&B[(size_t)(bn + row) * K + k0 + c4]);
            Bs[c4 + 0][row] = v.x;
            Bs[c4 + 1][row] = v.y;
            Bs[c4 + 2][row] = v.z;
            Bs[c4 + 3][row] = v.w;
        }
        __syncthreads();

        #pragma unroll
        for (int kk = 0; kk < BK; kk++) {
            float rm[TM], rn[TN];
            #pragma unroll
            for (int i = 0; i < TM; i++) rm[i] = As[kk][ty * TM + i];
            #pragma unroll
            for (int j = 0; j < TN; j++) rn[j] = Bs[kk][tx * TN + j];
            #pragma unroll
            for (int i = 0; i < TM; i++)
                #pragma unroll
                for (int j = 0; j < TN; j++)
                    acc[i][j] = fmaf(rm[i], rn[j], acc[i][j]);
        }
        __syncthreads();
    }

    #pragma unroll
    for (int i = 0; i < TM; i++) {
        size_t r = (size_t)(bm + ty * TM + i);
        #pragma unroll
        for (int j = 0; j < TN; j += 4) {
            int cc = bn + tx * TN + j;
            float4 o;
            o.x = acc[i][j + 0] + bias[cc + 0];
            o.y = acc[i][j + 1] + bias[cc + 1];
            o.z = acc[i][j + 2] + bias[cc + 2];
            o.w = acc[i][j + 3] + bias[cc + 3];
            *reinterpret_cast<float4*>(&C[r * N + cc]) = o;
        }
    }
}

extern "C" void kernel_launch(void* const* d_in, const int* in_sizes, int n_in,
                              void* d_out, int out_size) {
    const float* x  = (const float*)d_in[0];
    const float* W1 = (const float*)d_in[1];
    const float* b1 = (const float*)d_in[2];
    const float* W2 = (const float*)d_in[3];
    const float* b2 = (const float*)d_in[4];
    const float* W3 = (const float*)d_in[5];
    const float* b3 = (const float*)d_in[6];
    float* out = (float*)d_out;

    float *buf0 = nullptr, *buf1 = nullptr;
    cudaGetSymbolAddress((void**)&buf0, g_buf0);
    cudaGetSymbolAddress((void**)&buf1, g_buf1);

    // t1 = logmap0(x)
    prep_kernel<<<NROWS, 256>>>(x, buf0);

    // y1 = t1 @ W1^T + b1
    {
        dim3 grid(DHID / 128, NROWS / 128);
        gemm_tn_bias<<<grid, 256>>>(buf0, W1, b1, buf1, NROWS, DHID, DIN);
    }
    // t2 = fused(expmap0/projx/logmap0 roundtrips)(y1)
    transform_kernel<<<NROWS, 256>>>(buf1, buf0, DHID);

    // y2 = t2 @ W2^T + b2
    {
        dim3 grid(DHID / 128, NROWS / 128);
        gemm_tn_bias<<<grid, 256>>>(buf0, W2, b2, buf1, NROWS, DHID, DHID);
    }
    transform_kernel<<<NROWS, 256>>>(buf1, buf0, DHID);

    // y3 = t3 @ W3^T + b3
    {
        dim3 grid(DOUT / 128, NROWS / 128);
        gemm_tn_bias<<<grid, 256>>>(buf0, W3, b3, buf1, NROWS, DOUT, DHID);
    }
    // out = projx(safe_expmap0(y3))
    final_kernel<<<NROWS, 256>>>(buf1, out);
}

// round 2
// speedup vs baseline: 1.0011x; 1.0011x over previous
#include <cuda_runtime.h>
#include <math.h>

// Problem shape (fixed): N=8192, D_IN=1024, D_HID=4096, D_OUT=1024
#define NROWS 8192
#define DIN   1024
#define DHID  4096
#define DOUT  1024

// Scratch (allocation-free rule: __device__ globals). 128 MB each.
__device__ float g_buf0[NROWS * DHID];
__device__ float g_buf1[NROWS * DHID];

__device__ __forceinline__ float block_reduce_sum(float v) {
    __shared__ float sh[33];
    int lane = threadIdx.x & 31;
    int wid  = threadIdx.x >> 5;
    #pragma unroll
    for (int o = 16; o > 0; o >>= 1) v += __shfl_down_sync(0xffffffffu, v, o);
    if (lane == 0) sh[wid] = v;
    __syncthreads();
    if (wid == 0) {
        float t = (lane < (int)(blockDim.x >> 5)) ? sh[lane] : 0.0f;
        #pragma unroll
        for (int o = 16; o > 0; o >>= 1) t += __shfl_down_sync(0xffffffffu, t, o);
        if (lane == 0) sh[32] = t;
    }
    __syncthreads();
    return sh[32];
}

// Layer-1 prologue: t = logmap0(x_hyp). t[:,0]=0, t[:,j]=acosh(x0)/||xs|| * x[:,j]
// One block per row, 256 threads, D=1024 -> one float4 per thread.
__global__ __launch_bounds__(256) void prep_kernel(const float* __restrict__ x,
                                                   float* __restrict__ o) {
    int row = blockIdx.x;
    const float4* xr = reinterpret_cast<const float4*>(x + (size_t)row * DIN);
    float4* orow = reinterpret_cast<float4*>(o + (size_t)row * DIN);
    float4 v = xr[threadIdx.x];
    float ss;
    __shared__ float s_x0;
    if (threadIdx.x == 0) {
        s_x0 = v.x;
        ss = v.y * v.y + v.z * v.z + v.w * v.w;
    } else {
        ss = v.x * v.x + v.y * v.y + v.z * v.z + v.w * v.w;
    }
    float tot = block_reduce_sum(ss);
    float ns = fmaxf(sqrtf(tot), 1e-7f);
    float d = acoshf(fmaxf(s_x0, 1.0f + 1e-7f));
    float s = d / ns;
    float4 w;
    w.x = v.x * s; w.y = v.y * s; w.z = v.z * s; w.w = v.w * s;
    if (threadIdx.x == 0) w.x = 0.0f;
    orow[threadIdx.x] = w;
}

// Inter-layer fused nonlinearity: given y (N x D), next GEMM input is
// [0, min(||y[:,1:]||,10)/||y[:,1:]|| * y[:,1:]]  (all hyperbolic maps cancel)
__global__ __launch_bounds__(256) void transform_kernel(const float* __restrict__ y,
                                                        float* __restrict__ o, int D) {
    int row = blockIdx.x;
    const float4* yr = reinterpret_cast<const float4*>(y + (size_t)row * D);
    float4* orow = reinterpret_cast<float4*>(o + (size_t)row * D);
    int n4 = D >> 2;
    float ss = 0.0f;
    for (int i = threadIdx.x; i < n4; i += blockDim.x) {
        float4 v = yr[i];
        if (i == 0) ss += v.y * v.y + v.z * v.z + v.w * v.w;
        else        ss += v.x * v.x + v.y * v.y + v.z * v.z + v.w * v.w;
    }
    float n = fmaxf(sqrtf(block_reduce_sum(ss)), 1e-7f);
    float f = fminf(n, 10.0f) / n;
    for (int i = threadIdx.x; i < n4; i += blockDim.x) {
        float4 v = yr[i];
        float4 w;
        w.x = v.x * f; w.y = v.y * f; w.z = v.z * f; w.w = v.w * f;
        if (i == 0) w.x = 0.0f;
        orow[i] = w;
    }
}

// Final epilogue: out = [cosh(nc), sinh(nc)/n * y[:,1:]], nc = min(n,10)
__global__ __launch_bounds__(256) void final_kernel(const float* __restrict__ y,
                                                    float* __restrict__ o) {
    int row = blockIdx.x;
    const float4* yr = reinterpret_cast<const float4*>(y + (size_t)row * DOUT);
    float4* orow = reinterpret_cast<float4*>(o + (size_t)row * DOUT);
    float4 v = yr[threadIdx.x];
    float ss;
    if (threadIdx.x == 0) ss = v.y * v.y + v.z * v.z + v.w * v.w;
    else                  ss = v.x * v.x + v.y * v.y + v.z * v.z + v.w * v.w;
    float n = fmaxf(sqrtf(block_reduce_sum(ss)), 1e-7f);
    float nc = fminf(n, 10.0f);
    float f = sinhf(nc) / n;
    float4 w;
    w.x = v.x * f; w.y = v.y * f; w.z = v.z * f; w.w = v.w * f;
    if (threadIdx.x == 0) w.x = coshf(nc);
    orow[threadIdx.x] = w;
}

// C[M,N] = A[M,K] * B[N,K]^T + bias[N]   (both row-major, K inner: TN GEMM)
// Tile 128x128x16, 256 threads, 8x8 per thread.
__global__ __launch_bounds__(256) void gemm_tn_bias(const float* __restrict__ A,
                                                    const float* __restrict__ B,
                                                    const float* __restrict__ bias,
                                                    float* __restrict__ C,
                                                    int M, int N, int K) {
    const int BM = 128, BN = 128, BK = 16, TM = 8, TN = 8;
    __shared__ float As[BK][BM];
    __shared__ float Bs[BK][BN];
    const int bm = blockIdx.y * BM;
    const int bn = blockIdx.x * BN;
    const int tid = threadIdx.x;
    const int tx = tid & 15;   // N-dim
    const int ty = tid >> 4;   // M-dim

    float acc[TM][TN];
    #pragma unroll
    for (int i = 0; i < TM; i++)
        #pragma unroll
        for (int j = 0; j < TN; j++) acc[i][j] = 0.0f;

    for (int k0 = 0; k0 < K; k0 += BK) {
        // Load A tile (128x16) as float4, store transposed [k][m]
        #pragma unroll
        for (int it = 0; it < 2; ++it) {
            int idx = tid + it * 256;        // 0..511 float4 slots
            int row = idx >> 2;
            int c4  = (idx & 3) << 2;
            float4 v = *reinterpret_cast<const float4*>(&A[(size_t)(bm + row) * K + k0 + c4]);
            As[c4 + 0][row] = v.x;
            As[c4 + 1][row] = v.y;
            As[c4 + 2][row] = v.z;
            As[c4 + 3][row] = v.w;
        }
        // Load B tile (128x16)
        #pragma unroll
        for (int it = 0; it < 2; ++it) {
            int idx = tid + it * 256;
            int row = idx >> 2;
            int c4  = (idx & 3) << 2;
            float4 v = *reinterpret_cast<const float4*>(&B[(size_t)(bn + row) * K + k0 + c4]);
            Bs[c4 + 0][row] = v.x;
            Bs[c4 + 1][row] = v.y;
            Bs[c4 + 2][row] = v.z;
            Bs[c4 + 3][row] = v.w;
        }
        __syncthreads();

        #pragma unroll
        for (int kk = 0; kk < BK; kk++) {
            float rm[TM], rn[TN];
            #pragma unroll
            for (int i = 0; i < TM; i++) rm[i] = As[kk][ty * TM + i];
            #pragma unroll
            for (int j = 0; j < TN; j++) rn[j] = Bs[kk][tx * TN + j];
            #pragma unroll
            for (int i = 0; i < TM; i++)
                #pragma unroll
                for (int j = 0; j < TN; j++)
                    acc[i][j] = fmaf(rm[i], rn[j], acc[i][j]);
        }
        __syncthreads();
    }

    #pragma unroll
    for (int i = 0; i < TM; i++) {
        size_t r = (size_t)(bm + ty * TM + i);
        #pragma unroll
        for (int j = 0; j < TN; j += 4) {
            int cc = bn + tx * TN + j;
            float4 o;
            o.x = acc[i][j + 0] + bias[cc + 0];
            o.y = acc[i][j + 1] + bias[cc + 1];
            o.z = acc[i][j + 2] + bias[cc + 2];
            o.w = acc[i][j + 3] + bias[cc + 3];
            *reinterpret_cast<float4*>(&C[r * N + cc]) = o;
        }
    }
}

extern "C" void kernel_launch(void* const* d_in, const int* in_sizes, int n_in,
                              void* d_out, int out_size) {
    const float* x  = (const float*)d_in[0];
    const float* W1 = (const float*)d_in[1];
    const float* b1 = (const float*)d_in[2];
    const float* W2 = (const float*)d_in[3];
    const float* b2 = (const float*)d_in[4];
    const float* W3 = (const float*)d_in[5];
    const float* b3 = (const float*)d_in[6];
    float* out = (float*)d_out;

    float *buf0 = nullptr, *buf1 = nullptr;
    cudaGetSymbolAddress((void**)&buf0, g_buf0);
    cudaGetSymbolAddress((void**)&buf1, g_buf1);

    // t1 = logmap0(x)
    prep_kernel<<<NROWS, 256>>>(x, buf0);

    // y1 = t1 @ W1^T + b1
    {
        dim3 grid(DHID / 128, NROWS / 128);
        gemm_tn_bias<<<grid, 256>>>(buf0, W1, b1, buf1, NROWS, DHID, DIN);
    }
    // t2 = fused(expmap0/projx/logmap0 roundtrips)(y1)
    transform_kernel<<<NROWS, 256>>>(buf1, buf0, DHID);

    // y2 = t2 @ W2^T + b2
    {
        dim3 grid(DHID / 128, NROWS / 128);
        gemm_tn_bias<<<grid, 256>>>(buf0, W2, b2, buf1, NROWS, DHID, DHID);
    }
    transform_kernel<<<NROWS, 256>>>(buf1, buf0, DHID);

    // y3 = t3 @ W3^T + b3
    {
        dim3 grid(DOUT / 128, NROWS / 128);
        gemm_tn_bias<<<grid, 256>>>(buf0, W3, b3, buf1, NROWS, DOUT, DHID);
    }
    // out = projx(safe_expmap0(y3))
    final_kernel<<<NROWS, 256>>>(buf1, out);
}

// round 5
// speedup vs baseline: 3.5865x; 3.5827x over previous
#include <cuda_runtime.h>
#include <math.h>
#include <cstdint>

#define NROWS 8192
#define DIN   1024
#define DHID  4096
#define DOUT  1024

__device__ float g_buf0[NROWS * DHID];
__device__ float g_buf1[NROWS * DHID];

// ───────────────────────── elementwise helpers ─────────────────────────
__device__ __forceinline__ float block_reduce_sum(float v) {
    __shared__ float sh[33];
    int lane = threadIdx.x & 31;
    int wid  = threadIdx.x >> 5;
    #pragma unroll
    for (int o = 16; o > 0; o >>= 1) v += __shfl_down_sync(0xffffffffu, v, o);
    if (lane == 0) sh[wid] = v;
    __syncthreads();
    if (wid == 0) {
        float t = (lane < (int)(blockDim.x >> 5)) ? sh[lane] : 0.0f;
        #pragma unroll
        for (int o = 16; o > 0; o >>= 1) t += __shfl_down_sync(0xffffffffu, t, o);
        if (lane == 0) sh[32] = t;
    }
    __syncthreads();
    return sh[32];
}

__global__ __launch_bounds__(256) void prep_kernel(const float* __restrict__ x,
                                                   float* __restrict__ o) {
    int row = blockIdx.x;
    const float4* xr = reinterpret_cast<const float4*>(x + (size_t)row * DIN);
    float4* orow = reinterpret_cast<float4*>(o + (size_t)row * DIN);
    float4 v = xr[threadIdx.x];
    float ss;
    __shared__ float s_x0;
    if (threadIdx.x == 0) {
        s_x0 = v.x;
        ss = v.y * v.y + v.z * v.z + v.w * v.w;
    } else {
        ss = v.x * v.x + v.y * v.y + v.z * v.z + v.w * v.w;
    }
    float tot = block_reduce_sum(ss);
    float ns = fmaxf(sqrtf(tot), 1e-7f);
    float d = acoshf(fmaxf(s_x0, 1.0f + 1e-7f));
    float s = d / ns;
    float4 w;
    w.x = v.x * s; w.y = v.y * s; w.z = v.z * s; w.w = v.w * s;
    if (threadIdx.x == 0) w.x = 0.0f;
    orow[threadIdx.x] = w;
}

__global__ __launch_bounds__(256) void transform_kernel(const float* __restrict__ y,
                                                        float* __restrict__ o, int D) {
    int row = blockIdx.x;
    const float4* yr = reinterpret_cast<const float4*>(y + (size_t)row * D);
    float4* orow = reinterpret_cast<float4*>(o + (size_t)row * D);
    int n4 = D >> 2;
    float ss = 0.0f;
    for (int i = threadIdx.x; i < n4; i += blockDim.x) {
        float4 v = yr[i];
        if (i == 0) ss += v.y * v.y + v.z * v.z + v.w * v.w;
        else        ss += v.x * v.x + v.y * v.y + v.z * v.z + v.w * v.w;
    }
    float n = fmaxf(sqrtf(block_reduce_sum(ss)), 1e-7f);
    float f = fminf(n, 10.0f) / n;
    for (int i = threadIdx.x; i < n4; i += blockDim.x) {
        float4 v = yr[i];
        float4 w;
        w.x = v.x * f; w.y = v.y * f; w.z = v.z * f; w.w = v.w * f;
        if (i == 0) w.x = 0.0f;
        orow[i] = w;
    }
}

__global__ __launch_bounds__(256) void final_kernel(const float* __restrict__ y,
                                                    float* __restrict__ o) {
    int row = blockIdx.x;
    const float4* yr = reinterpret_cast<const float4*>(y + (size_t)row * DOUT);
    float4* orow = reinterpret_cast<float4*>(o + (size_t)row * DOUT);
    float4 v = yr[threadIdx.x];
    float ss;
    if (threadIdx.x == 0) ss = v.y * v.y + v.z * v.z + v.w * v.w;
    else                  ss = v.x * v.x + v.y * v.y + v.z * v.z + v.w * v.w;
    float n = fmaxf(sqrtf(block_reduce_sum(ss)), 1e-7f);
    float nc = fminf(n, 10.0f);
    float f = sinhf(nc) / n;
    float4 w;
    w.x = v.x * f; w.y = v.y * f; w.z = v.z * f; w.w = v.w * f;
    if (threadIdx.x == 0) w.x = coshf(nc);
    orow[threadIdx.x] = w;
}

// ───────────────────────── mma.sync tf32 GEMM ─────────────────────────
// C[M,Nn] = A[M,K] @ B[Nn,K]^T + bias.  Both row-major, K contiguous (TN).
// CTA tile 128x128x32, 8 warps, warp tile 64x32 (4 m16 x 4 n8, k8 steps).
// Double-buffered cp.async pipeline. SMEM rows padded to 36 floats.

#define BM 128
#define BN 128
#define BK 32
#define SPAD 36                    // 32 + 4 pad
#define STAGE_FLOATS (128 * SPAD)  // per tile per stage
#define SMEM_TOTAL (4 * STAGE_FLOATS * 4)  // A(2 stages) + B(2 stages), bytes

#define CP_ASYNC16(dst, src) \
    asm volatile("cp.async.cg.shared.global [%0], [%1], 16;\n" :: "r"(dst), "l"(src))
#define CP_COMMIT() asm volatile("cp.async.commit_group;\n" ::: "memory")
#define CP_WAIT1()  asm volatile("cp.async.wait_group 1;\n" ::: "memory")

__device__ __forceinline__ uint32_t smem_u32(const void* p) {
    uint32_t a;
    asm("{ .reg .u64 t; cvta.to.shared.u64 t, %1; cvt.u32.u64 %0, t; }" : "=r"(a) : "l"(p));
    return a;
}
__device__ __forceinline__ uint32_t f2tf32(float f) {
    uint32_t u;
    asm("cvt.rna.tf32.f32 %0, %1;" : "=r"(u) : "f"(f));
    return u;
}
__device__ __forceinline__ void mma_tf32(float& d0, float& d1, float& d2, float& d3,
                                         uint32_t a0, uint32_t a1, uint32_t a2, uint32_t a3,
                                         uint32_t b0, uint32_t b1) {
    asm volatile(
        "mma.sync.aligned.m16n8k8.row.col.f32.tf32.tf32.f32 "
        "{%0,%1,%2,%3}, {%4,%5,%6,%7}, {%8,%9}, {%0,%1,%2,%3};"
        : "+f"(d0), "+f"(d1), "+f"(d2), "+f"(d3)
        : "r"(a0), "r"(a1), "r"(a2), "r"(a3), "r"(b0), "r"(b1));
}

__global__ __launch_bounds__(256, 1) void gemm_mma_tf32(const float* __restrict__ A,
                                                        const float* __restrict__ B,
                                                        const float* __restrict__ bias,
                                                        float* __restrict__ C,
                                                        int M, int Nn, int K) {
    extern __shared__ float smem[];
    float* As = smem;                       // 2 stages of 128 x SPAD
    float* Bs = smem + 2 * STAGE_FLOATS;    // 2 stages of 128 x SPAD

    const int tid  = threadIdx.x;
    const int wid  = tid >> 5;
    const int lane = tid & 31;
    const int g    = lane >> 2;     // group id (row within m8/n8)
    const int q    = lane & 3;      // thread-in-group (col/k)

    const int bm = blockIdx.y * BM;
    const int bn = blockIdx.x * BN;
    const int wm = (wid & 1) * 64;  // warp M base within CTA tile
    const int wn = (wid >> 1) * 32; // warp N base

    // cp.async slot mapping: 1024 float4 slots per tile, 4 per thread
    const int lrow = tid >> 1;            // 0..127 (two threads per row)
    const int lc4a = (tid & 1) * 2;       // c4 in {0,1} pairs -> cols {0,4} / {8,12}... below
    const uint32_t as_base = smem_u32(As);
    const uint32_t bs_base = smem_u32(Bs);

    float acc[4][4][4];
    #pragma unroll
    for (int i = 0; i < 4; i++)
        #pragma unroll
        for (int j = 0; j < 4; j++)
            #pragma unroll
            for (int r = 0; r < 4; r++) acc[i][j][r] = 0.0f;

    const int NC = K / BK;

    // stage load: A/B tile rows [0,128), 8 float4 per row. Thread does 4 float4
    // per tile: rows lrow, cols (lc4a + {0,1})*... use: each thread: row=tid>>1,
    // float4 cols {lc4a, lc4a+1} and {lc4a+4, lc4a+5}? Simpler: 256 threads x 4
    // iterations over 1024 slots: slot = tid + it*256 -> row = slot>>3, c4 = slot&7.
    auto load_stage = [&](int c, int s) {
        const float* Ab = A + (size_t)bm * K + (size_t)c * BK;
        const float* Bb = B + (size_t)bn * K + (size_t)c * BK;
        const uint32_t aoff = as_base + s * STAGE_FLOATS * 4;
        const uint32_t boff = bs_base + s * STAGE_FLOATS * 4;
        #pragma unroll
        for (int it = 0; it < 4; it++) {
            int slot = tid + it * 256;
            int r = slot >> 3, c4 = slot & 7;
            CP_ASYNC16(aoff + (r * SPAD + c4 * 4) * 4, Ab + (size_t)r * K + c4 * 4);
        }
        #pragma unroll
        for (int it = 0; it < 4; it++) {
            int slot = tid + it * 256;
            int r = slot >> 3, c4 = slot & 7;
            CP_ASYNC16(boff + (r * SPAD + c4 * 4) * 4, Bb + (size_t)r * K + c4 * 4);
        }
    };

    load_stage(0, 0);
    CP_COMMIT();

    for (int c = 0; c < NC; c++) {
        const int s = c & 1;
        if (c + 1 < NC) load_stage(c + 1, (c + 1) & 1);
        CP_COMMIT();
        CP_WAIT1();
        __syncthreads();

        const float* Ats = As + s * STAGE_FLOATS;
        const float* Bts = Bs + s * STAGE_FLOATS;

        #pragma unroll
        for (int ks = 0; ks < 4; ks++) {
            const int k = ks * 8 + q;
            uint32_t af[4][4];
            #pragma unroll
            for (int mt = 0; mt < 4; mt++) {
                const int row = wm + mt * 16 + g;
                af[mt][0] = f2tf32(Ats[row * SPAD + k]);
                af[mt][1] = f2tf32(Ats[(row + 8) * SPAD + k]);
                af[mt][2] = f2tf32(Ats[row * SPAD + k + 4]);
                af[mt][3] = f2tf32(Ats[(row + 8) * SPAD + k + 4]);
            }
            uint32_t bf[4][2];
            #pragma unroll
            for (int nt = 0; nt < 4; nt++) {
                const int n = wn + nt * 8 + g;
                bf[nt][0] = f2tf32(Bts[n * SPAD + k]);
                bf[nt][1] = f2tf32(Bts[n * SPAD + k + 4]);
            }
            #pragma unroll
            for (int mt = 0; mt < 4; mt++)
                #pragma unroll
                for (int nt = 0; nt < 4; nt++)
                    mma_tf32(acc[mt][nt][0], acc[mt][nt][1], acc[mt][nt][2], acc[mt][nt][3],
                             af[mt][0], af[mt][1], af[mt][2], af[mt][3],
                             bf[nt][0], bf[nt][1]);
        }
        __syncthreads();
    }

    // Epilogue: c0,c1 -> (row, col2..col2+1); c2,c3 -> (row+8, col2..col2+1)
    #pragma unroll
    for (int mt = 0; mt < 4; mt++) {
        const int r0 = bm + wm + mt * 16 + g;
        #pragma unroll
        for (int nt = 0; nt < 4; nt++) {
            const int c0 = bn + wn + nt * 8 + q * 2;
            float2 bv = *reinterpret_cast<const float2*>(bias + c0);
            float2 o0, o1;
            o0.x = acc[mt][nt][0] + bv.x;
            o0.y = acc[mt][nt][1] + bv.y;
            o1.x = acc[mt][nt][2] + bv.x;
            o1.y = acc[mt][nt][3] + bv.y;
            *reinterpret_cast<float2*>(&C[(size_t)r0 * Nn + c0]) = o0;
            *reinterpret_cast<float2*>(&C[(size_t)(r0 + 8) * Nn + c0]) = o1;
        }
    }
}

// ───────────────────────── launch ─────────────────────────
extern "C" void kernel_launch(void* const* d_in, const int* in_sizes, int n_in,
                              void* d_out, int out_size) {
    const float* x  = (const float*)d_in[0];
    const float* W1 = (const float*)d_in[1];
    const float* b1 = (const float*)d_in[2];
    const float* W2 = (const float*)d_in[3];
    const float* b2 = (const float*)d_in[4];
    const float* W3 = (const float*)d_in[5];
    const float* b3 = (const float*)d_in[6];
    float* out = (float*)d_out;

    float *buf0 = nullptr, *buf1 = nullptr;
    cudaGetSymbolAddress((void**)&buf0, g_buf0);
    cudaGetSymbolAddress((void**)&buf1, g_buf1);

    cudaFuncSetAttribute(gemm_mma_tf32, cudaFuncAttributeMaxDynamicSharedMemorySize, SMEM_TOTAL);

    // t1 = logmap0(x)
    prep_kernel<<<NROWS, 256>>>(x, buf0);

    // y1 = t1 @ W1^T + b1   (K=1024, N=4096)
    {
        dim3 grid(DHID / BN, NROWS / BM);
        gemm_mma_tf32<<<grid, 256, SMEM_TOTAL>>>(buf0, W1, b1, buf1, NROWS, DHID, DIN);
    }
    transform_kernel<<<NROWS, 256>>>(buf1, buf0, DHID);

    // y2 = t2 @ W2^T + b2   (K=4096, N=4096)
    {
        dim3 grid(DHID / BN, NROWS / BM);
        gemm_mma_tf32<<<grid, 256, SMEM_TOTAL>>>(buf0, W2, b2, buf1, NROWS, DHID, DHID);
    }
    transform_kernel<<<NROWS, 256>>>(buf1, buf0, DHID);

    // y3 = t3 @ W3^T + b3   (K=4096, N=1024)
    {
        dim3 grid(DOUT / BN, NROWS / BM);
        gemm_mma_tf32<<<grid, 256, SMEM_TOTAL>>>(buf0, W3, b3, buf1, NROWS, DOUT, DHID);
    }
    final_kernel<<<NROWS, 256>>>(buf1, out);
}

// round 10
// speedup vs baseline: 4.2289x; 1.1791x over previous
#include <cuda_runtime.h>
#include <math.h>
#include <cstdint>

#define NROWS 8192
#define DIN   1024
#define DHID  4096
#define DOUT  1024

__device__ float g_buf0[NROWS * DHID];
__device__ float g_buf1[NROWS * DHID];
__device__ float g_w1r[DHID * DIN];
__device__ float g_w2r[DHID * DHID];
__device__ float g_w3r[DOUT * DHID];

// ───────────────────────── low-level helpers ─────────────────────────
__device__ __forceinline__ uint32_t smem_u32(const void* p) {
    uint32_t a;
    asm("{ .reg .u64 t; cvta.to.shared.u64 t, %1; cvt.u32.u64 %0, t; }" : "=r"(a) : "l"(p));
    return a;
}
__device__ __forceinline__ float tf32r(float f) {
    uint32_t u;
    asm("cvt.rna.tf32.f32 %0, %1;" : "=r"(u) : "f"(f));
    return __uint_as_float(u);
}
__device__ __forceinline__ void ldsm_x4(uint32_t& r0, uint32_t& r1, uint32_t& r2, uint32_t& r3,
                                        uint32_t addr) {
    asm volatile("ldmatrix.sync.aligned.m8n8.x4.shared.b16 {%0,%1,%2,%3}, [%4];"
                 : "=r"(r0), "=r"(r1), "=r"(r2), "=r"(r3) : "r"(addr));
}
__device__ __forceinline__ void mma_tf32(float& d0, float& d1, float& d2, float& d3,
                                         uint32_t a0, uint32_t a1, uint32_t a2, uint32_t a3,
                                         uint32_t b0, uint32_t b1) {
    asm volatile(
        "mma.sync.aligned.m16n8k8.row.col.f32.tf32.tf32.f32 "
        "{%0,%1,%2,%3}, {%4,%5,%6,%7}, {%8,%9}, {%0,%1,%2,%3};"
        : "+f"(d0), "+f"(d1), "+f"(d2), "+f"(d3)
        : "r"(a0), "r"(a1), "r"(a2), "r"(a3), "r"(b0), "r"(b1));
}
#define CP_ASYNC16(dst, src) \
    asm volatile("cp.async.cg.shared.global [%0], [%1], 16;\n" :: "r"(dst), "l"(src))
#define CP_COMMIT()  asm volatile("cp.async.commit_group;\n" ::: "memory")
#define CP_WAIT3()   asm volatile("cp.async.wait_group 3;\n" ::: "memory")
#define CP_WAIT0()   asm volatile("cp.async.wait_group 0;\n" ::: "memory")

// ───────────────────────── elementwise kernels ─────────────────────────
__device__ __forceinline__ float block_reduce_sum(float v) {
    __shared__ float sh[33];
    int lane = threadIdx.x & 31;
    int wid  = threadIdx.x >> 5;
    #pragma unroll
    for (int o = 16; o > 0; o >>= 1) v += __shfl_down_sync(0xffffffffu, v, o);
    if (lane == 0) sh[wid] = v;
    __syncthreads();
    if (wid == 0) {
        float t = (lane < (int)(blockDim.x >> 5)) ? sh[lane] : 0.0f;
        #pragma unroll
        for (int o = 16; o > 0; o >>= 1) t += __shfl_down_sync(0xffffffffu, t, o);
        if (lane == 0) sh[32] = t;
    }
    __syncthreads();
    return sh[32];
}

__global__ __launch_bounds__(256) void round_tf32_kernel(const float4* __restrict__ in,
                                                         float4* __restrict__ out, int n4) {
    int i = blockIdx.x * blockDim.x + threadIdx.x;
    if (i < n4) {
        float4 v = in[i];
        v.x = tf32r(v.x); v.y = tf32r(v.y); v.z = tf32r(v.z); v.w = tf32r(v.w);
        out[i] = v;
    }
}

// t = logmap0(x), output rounded to tf32 (GEMM input)
__global__ __launch_bounds__(256) void prep_kernel(const float* __restrict__ x,
                                                   float* __restrict__ o) {
    int row = blockIdx.x;
    const float4* xr = reinterpret_cast<const float4*>(x + (size_t)row * DIN);
    float4* orow = reinterpret_cast<float4*>(o + (size_t)row * DIN);
    float4 v = xr[threadIdx.x];
    float ss;
    __shared__ float s_x0;
    if (threadIdx.x == 0) {
        s_x0 = v.x;
        ss = v.y * v.y + v.z * v.z + v.w * v.w;
    } else {
        ss = v.x * v.x + v.y * v.y + v.z * v.z + v.w * v.w;
    }
    float tot = block_reduce_sum(ss);
    float ns = fmaxf(sqrtf(tot), 1e-7f);
    float d = acoshf(fmaxf(s_x0, 1.0f + 1e-7f));
    float s = d / ns;
    float4 w;
    w.x = tf32r(v.x * s); w.y = tf32r(v.y * s); w.z = tf32r(v.z * s); w.w = tf32r(v.w * s);
    if (threadIdx.x == 0) w.x = 0.0f;
    orow[threadIdx.x] = w;
}

// inter-layer collapse; output rounded to tf32 (GEMM input)
__global__ __launch_bounds__(256) void transform_kernel(const float* __restrict__ y,
                                                        float* __restrict__ o, int D) {
    int row = blockIdx.x;
    const float4* yr = reinterpret_cast<const float4*>(y + (size_t)row * D);
    float4* orow = reinterpret_cast<float4*>(o + (size_t)row * D);
    int n4 = D >> 2;
    float ss = 0.0f;
    for (int i = threadIdx.x; i < n4; i += blockDim.x) {
        float4 v = yr[i];
        if (i == 0) ss += v.y * v.y + v.z * v.z + v.w * v.w;
        else        ss += v.x * v.x + v.y * v.y + v.z * v.z + v.w * v.w;
    }
    float n = fmaxf(sqrtf(block_reduce_sum(ss)), 1e-7f);
    float f = fminf(n, 10.0f) / n;
    for (int i = threadIdx.x; i < n4; i += blockDim.x) {
        float4 v = yr[i];
        float4 w;
        w.x = tf32r(v.x * f); w.y = tf32r(v.y * f); w.z = tf32r(v.z * f); w.w = tf32r(v.w * f);
        if (i == 0) w.x = 0.0f;
        orow[i] = w;
    }
}

__global__ __launch_bounds__(256) void final_kernel(const float* __restrict__ y,
                                                    float* __restrict__ o) {
    int row = blockIdx.x;
    const float4* yr = reinterpret_cast<const float4*>(y + (size_t)row * DOUT);
    float4* orow = reinterpret_cast<float4*>(o + (size_t)row * DOUT);
    float4 v = yr[threadIdx.x];
    float ss;
    if (threadIdx.x == 0) ss = v.y * v.y + v.z * v.z + v.w * v.w;
    else                  ss = v.x * v.x + v.y * v.y + v.z * v.z + v.w * v.w;
    float n = fmaxf(sqrtf(block_reduce_sum(ss)), 1e-7f);
    float nc = fminf(n, 10.0f);
    float f = sinhf(nc) / n;
    float4 w;
    w.x = v.x * f; w.y = v.y * f; w.z = v.z * f; w.w = v.w * f;
    if (threadIdx.x == 0) w.x = coshf(nc);
    orow[threadIdx.x] = w;
}

// ───────────────────────── mma.sync tf32 GEMM, ldmatrix + 4-stage pipeline ─────────────
// C[M,Nn] = A[M,K] @ B[Nn,K]^T + bias.  Inputs pre-rounded to tf32.
// CTA 128x128x32, 8 warps, warp tile 64x32. SMEM rows = 32 floats (128B),
// 16B-chunk XOR swizzle: chunk' = chunk ^ (row & 7).

#define BM 128
#define BN 128
#define BK 32
#define NSTAGE 4
#define STAGE_BYTES (128 * 128)          // 128 rows x 128B
#define SMEM_TOTAL (2 * NSTAGE * STAGE_BYTES)

__global__ __launch_bounds__(256, 1) void gemm_mma_tf32(const float* __restrict__ A,
                                                        const float* __restrict__ B,
                                                        const float* __restrict__ bias,
                                                        float* __restrict__ C,
                                                        int M, int Nn, int K) {
    extern __shared__ char smem[];
    const uint32_t sbase = smem_u32(smem);          // A stages
    const uint32_t sbase_b = sbase + NSTAGE * STAGE_BYTES;

    const int tid  = threadIdx.x;
    const int wid  = tid >> 5;
    const int lane = tid & 31;
    const int g    = lane >> 2;
    const int q    = lane & 3;

    const int bm = blockIdx.y * BM;
    const int bn = blockIdx.x * BN;
    const int wm = (wid & 1) * 64;
    const int wn = (wid >> 1) * 32;

    // ldmatrix lane-address precompute
    const int mat = lane >> 3, r8 = lane & 7;
    uint32_t a_rowoff[4], a_xor[4];
    const uint32_t a_chi = (uint32_t)(mat >> 1);
    #pragma unroll
    for (int mt = 0; mt < 4; mt++) {
        int row = wm + mt * 16 + (mat & 1) * 8 + r8;
        a_rowoff[mt] = (uint32_t)row * 128u;
        a_xor[mt] = (uint32_t)(row & 7);
    }
    uint32_t b_rowoff[2], b_xor[2];
    const uint32_t b_chi = (uint32_t)(mat & 1);
    #pragma unroll
    for (int np = 0; np < 2; np++) {
        int row = wn + np * 16 + (mat >> 1) * 8 + r8;
        b_rowoff[np] = (uint32_t)row * 128u;
        b_xor[np] = (uint32_t)(row & 7);
    }

    float acc[4][4][4];
    #pragma unroll
    for (int i = 0; i < 4; i++)
        #pragma unroll
        for (int j = 0; j < 4; j++)
            #pragma unroll
            for (int r = 0; r < 4; r++) acc[i][j][r] = 0.0f;

    const int NC = K / BK;

    auto load_stage = [&](int c, int s) {
        const float* Ab = A + (size_t)bm * K + (size_t)c * BK;
        const float* Bb = B + (size_t)bn * K + (size_t)c * BK;
        const uint32_t ad = sbase + (uint32_t)s * STAGE_BYTES;
        const uint32_t bd = sbase_b + (uint32_t)s * STAGE_BYTES;
        #pragma unroll
        for (int it = 0; it < 4; it++) {
            int slot = tid + it * 256;
            int r = slot >> 3, c4 = slot & 7;
            uint32_t sw = (uint32_t)(c4 ^ (r & 7)) << 4;
            CP_ASYNC16(ad + (uint32_t)r * 128u + sw, Ab + (size_t)r * K + c4 * 4);
        }
        #pragma unroll
        for (int it = 0; it < 4; it++) {
            int slot = tid + it * 256;
            int r = slot >> 3, c4 = slot & 7;
            uint32_t sw = (uint32_t)(c4 ^ (r & 7)) << 4;
            CP_ASYNC16(bd + (uint32_t)r * 128u + sw, Bb + (size_t)r * K + c4 * 4);
        }
    };

    // prologue: stages 0..2
    #pragma unroll
    for (int s = 0; s < NSTAGE - 1; s++) {
        if (s < NC) load_stage(s, s);
        CP_COMMIT();
    }

    for (int c = 0; c < NC; c++) {
        const int s = c & (NSTAGE - 1);
        if (c + NSTAGE - 1 < NC) load_stage(c + NSTAGE - 1, (c + NSTAGE - 1) & (NSTAGE - 1));
        CP_COMMIT();
        CP_WAIT3();
        __syncthreads();

        const uint32_t ast = sbase + (uint32_t)s * STAGE_BYTES;
        const uint32_t bst = sbase_b + (uint32_t)s * STAGE_BYTES;

        #pragma unroll
        for (int ks = 0; ks < 4; ks++) {
            uint32_t af[4][4];
            #pragma unroll
            for (int mt = 0; mt < 4; mt++) {
                uint32_t addr = ast + a_rowoff[mt] +
                                ((((uint32_t)ks * 2u + a_chi) ^ a_xor[mt]) << 4);
                ldsm_x4(af[mt][0], af[mt][1], af[mt][2], af[mt][3], addr);
            }
            uint32_t bf[4][2];
            #pragma unroll
            for (int np = 0; np < 2; np++) {
                uint32_t addr = bst + b_rowoff[np] +
                                ((((uint32_t)ks * 2u + b_chi) ^ b_xor[np]) << 4);
                ldsm_x4(bf[2 * np][0], bf[2 * np][1], bf[2 * np + 1][0], bf[2 * np + 1][1], addr);
            }
            #pragma unroll
            for (int mt = 0; mt < 4; mt++)
                #pragma unroll
                for (int nt = 0; nt < 4; nt++)
                    mma_tf32(acc[mt][nt][0], acc[mt][nt][1], acc[mt][nt][2], acc[mt][nt][3],
                             af[mt][0], af[mt][1], af[mt][2], af[mt][3],
                             bf[nt][0], bf[nt][1]);
        }
        __syncthreads();
    }
    CP_WAIT0();

    // Epilogue
    #pragma unroll
    for (int mt = 0; mt < 4; mt++) {
        const int r0 = bm + wm + mt * 16 + g;
        #pragma unroll
        for (int nt = 0; nt < 4; nt++) {
            const int c0 = bn + wn + nt * 8 + q * 2;
            float2 bv = *reinterpret_cast<const float2*>(bias + c0);
            float2 o0, o1;
            o0.x = acc[mt][nt][0] + bv.x;
            o0.y = acc[mt][nt][1] + bv.y;
            o1.x = acc[mt][nt][2] + bv.x;
            o1.y = acc[mt][nt][3] + bv.y;
            *reinterpret_cast<float2*>(&C[(size_t)r0 * Nn + c0]) = o0;
            *reinterpret_cast<float2*>(&C[(size_t)(r0 + 8) * Nn + c0]) = o1;
        }
    }
}

// ───────────────────────── launch ─────────────────────────
extern "C" void kernel_launch(void* const* d_in, const int* in_sizes, int n_in,
                              void* d_out, int out_size) {
    const float* x  = (const float*)d_in[0];
    const float* W1 = (const float*)d_in[1];
    const float* b1 = (const float*)d_in[2];
    const float* W2 = (const float*)d_in[3];
    const float* b2 = (const float*)d_in[4];
    const float* W3 = (const float*)d_in[5];
    const float* b3 = (const float*)d_in[6];
    float* out = (float*)d_out;

    float *buf0, *buf1, *w1r, *w2r, *w3r;
    cudaGetSymbolAddress((void**)&buf0, g_buf0);
    cudaGetSymbolAddress((void**)&buf1, g_buf1);
    cudaGetSymbolAddress((void**)&w1r, g_w1r);
    cudaGetSymbolAddress((void**)&w2r, g_w2r);
    cudaGetSymbolAddress((void**)&w3r, g_w3r);

    cudaFuncSetAttribute(gemm_mma_tf32, cudaFuncAttributeMaxDynamicSharedMemorySize, SMEM_TOTAL);

    // Pre-round weights to tf32 (rna)
    round_tf32_kernel<<<(DHID * DIN / 4 + 255) / 256, 256>>>((const float4*)W1, (float4*)w1r, DHID * DIN / 4);
    round_tf32_kernel<<<(DHID * DHID / 4 + 255) / 256, 256>>>((const float4*)W2, (float4*)w2r, DHID * DHID / 4);
    round_tf32_kernel<<<(DOUT * DHID / 4 + 255) / 256, 256>>>((const float4*)W3, (float4*)w3r, DOUT * DHID / 4);

    // t1 = logmap0(x) (tf32-rounded)
    prep_kernel<<<NROWS, 256>>>(x, buf0);

    // y1 = t1 @ W1^T + b1
    {
        dim3 grid(DHID / BN, NROWS / BM);
        gemm_mma_tf32<<<grid, 256, SMEM_TOTAL>>>(buf0, w1r, b1, buf1, NROWS, DHID, DIN);
    }
    transform_kernel<<<NROWS, 256>>>(buf1, buf0, DHID);

    // y2 = t2 @ W2^T + b2
    {
        dim3 grid(DHID / BN, NROWS / BM);
        gemm_mma_tf32<<<grid, 256, SMEM_TOTAL>>>(buf0, w2r, b2, buf1, NROWS, DHID, DHID);
    }
    transform_kernel<<<NROWS, 256>>>(buf1, buf0, DHID);

    // y3 = t3 @ W3^T + b3
    {
        dim3 grid(DOUT / BN, NROWS / BM);
        gemm_mma_tf32<<<grid, 256, SMEM_TOTAL>>>(buf0, w3r, b3, buf1, NROWS, DOUT, DHID);
    }
    final_kernel<<<NROWS, 256>>>(buf1, out);
}

// round 11
// speedup vs baseline: 5.0695x; 1.1988x over previous
#include <cuda_runtime.h>
#include <math.h>
#include <cstdint>

#define NROWS 8192
#define DIN   1024
#define DHID  4096
#define DOUT  1024

__device__ float g_buf0[NROWS * DHID];
__device__ float g_buf1[NROWS * DHID];
__device__ float g_w1r[DHID * DIN];
__device__ float g_w2r[DHID * DHID];
__device__ float g_w3r[DOUT * DHID];

// ───────────────────────── low-level helpers ─────────────────────────
__device__ __forceinline__ uint32_t smem_u32(const void* p) {
    uint32_t a;
    asm("{ .reg .u64 t; cvta.to.shared.u64 t, %1; cvt.u32.u64 %0, t; }" : "=r"(a) : "l"(p));
    return a;
}
__device__ __forceinline__ float tf32r(float f) {
    uint32_t u;
    asm("cvt.rna.tf32.f32 %0, %1;" : "=r"(u) : "f"(f));
    return __uint_as_float(u);
}
__device__ __forceinline__ void ldsm_x4(uint32_t& r0, uint32_t& r1, uint32_t& r2, uint32_t& r3,
                                        uint32_t addr) {
    asm volatile("ldmatrix.sync.aligned.m8n8.x4.shared.b16 {%0,%1,%2,%3}, [%4];"
                 : "=r"(r0), "=r"(r1), "=r"(r2), "=r"(r3) : "r"(addr));
}
__device__ __forceinline__ void mma_tf32(float& d0, float& d1, float& d2, float& d3,
                                         uint32_t a0, uint32_t a1, uint32_t a2, uint32_t a3,
                                         uint32_t b0, uint32_t b1) {
    asm volatile(
        "mma.sync.aligned.m16n8k8.row.col.f32.tf32.tf32.f32 "
        "{%0,%1,%2,%3}, {%4,%5,%6,%7}, {%8,%9}, {%0,%1,%2,%3};"
        : "+f"(d0), "+f"(d1), "+f"(d2), "+f"(d3)
        : "r"(a0), "r"(a1), "r"(a2), "r"(a3), "r"(b0), "r"(b1));
}
#define CP_ASYNC16(dst, src) \
    asm volatile("cp.async.cg.shared.global [%0], [%1], 16;\n" :: "r"(dst), "l"(src))
#define CP_COMMIT()  asm volatile("cp.async.commit_group;\n" ::: "memory")
#define CP_WAIT2()   asm volatile("cp.async.wait_group 2;\n" ::: "memory")
#define CP_WAIT0()   asm volatile("cp.async.wait_group 0;\n" ::: "memory")

// ───────────────────────── elementwise kernels ─────────────────────────
__device__ __forceinline__ float block_reduce_sum(float v) {
    __shared__ float sh[33];
    int lane = threadIdx.x & 31;
    int wid  = threadIdx.x >> 5;
    #pragma unroll
    for (int o = 16; o > 0; o >>= 1) v += __shfl_down_sync(0xffffffffu, v, o);
    if (lane == 0) sh[wid] = v;
    __syncthreads();
    if (wid == 0) {
        float t = (lane < (int)(blockDim.x >> 5)) ? sh[lane] : 0.0f;
        #pragma unroll
        for (int o = 16; o > 0; o >>= 1) t += __shfl_down_sync(0xffffffffu, t, o);
        if (lane == 0) sh[32] = t;
    }
    __syncthreads();
    return sh[32];
}

__global__ __launch_bounds__(256) void round_tf32_kernel(const float4* __restrict__ in,
                                                         float4* __restrict__ out, int n4) {
    int i = blockIdx.x * blockDim.x + threadIdx.x;
    if (i < n4) {
        float4 v = in[i];
        v.x = tf32r(v.x); v.y = tf32r(v.y); v.z = tf32r(v.z); v.w = tf32r(v.w);
        out[i] = v;
    }
}

// t = logmap0(x), output rounded to tf32 (GEMM input)
__global__ __launch_bounds__(256) void prep_kernel(const float* __restrict__ x,
                                                   float* __restrict__ o) {
    int row = blockIdx.x;
    const float4* xr = reinterpret_cast<const float4*>(x + (size_t)row * DIN);
    float4* orow = reinterpret_cast<float4*>(o + (size_t)row * DIN);
    float4 v = xr[threadIdx.x];
    float ss;
    __shared__ float s_x0;
    if (threadIdx.x == 0) {
        s_x0 = v.x;
        ss = v.y * v.y + v.z * v.z + v.w * v.w;
    } else {
        ss = v.x * v.x + v.y * v.y + v.z * v.z + v.w * v.w;
    }
    float tot = block_reduce_sum(ss);
    float ns = fmaxf(sqrtf(tot), 1e-7f);
    float d = acoshf(fmaxf(s_x0, 1.0f + 1e-7f));
    float s = d / ns;
    float4 w;
    w.x = tf32r(v.x * s); w.y = tf32r(v.y * s); w.z = tf32r(v.z * s); w.w = tf32r(v.w * s);
    if (threadIdx.x == 0) w.x = 0.0f;
    orow[threadIdx.x] = w;
}

// inter-layer collapse; output rounded to tf32 (GEMM input)
__global__ __launch_bounds__(256) void transform_kernel(const float* __restrict__ y,
                                                        float* __restrict__ o, int D) {
    int row = blockIdx.x;
    const float4* yr = reinterpret_cast<const float4*>(y + (size_t)row * D);
    float4* orow = reinterpret_cast<float4*>(o + (size_t)row * D);
    int n4 = D >> 2;
    float ss = 0.0f;
    for (int i = threadIdx.x; i < n4; i += blockDim.x) {
        float4 v = yr[i];
        if (i == 0) ss += v.y * v.y + v.z * v.z + v.w * v.w;
        else        ss += v.x * v.x + v.y * v.y + v.z * v.z + v.w * v.w;
    }
    float n = fmaxf(sqrtf(block_reduce_sum(ss)), 1e-7f);
    float f = fminf(n, 10.0f) / n;
    for (int i = threadIdx.x; i < n4; i += blockDim.x) {
        float4 v = yr[i];
        float4 w;
        w.x = tf32r(v.x * f); w.y = tf32r(v.y * f); w.z = tf32r(v.z * f); w.w = tf32r(v.w * f);
        if (i == 0) w.x = 0.0f;
        orow[i] = w;
    }
}

__global__ __launch_bounds__(256) void final_kernel(const float* __restrict__ y,
                                                    float* __restrict__ o) {
    int row = blockIdx.x;
    const float4* yr = reinterpret_cast<const float4*>(y + (size_t)row * DOUT);
    float4* orow = reinterpret_cast<float4*>(o + (size_t)row * DOUT);
    float4 v = yr[threadIdx.x];
    float ss;
    if (threadIdx.x == 0) ss = v.y * v.y + v.z * v.z + v.w * v.w;
    else                  ss = v.x * v.x + v.y * v.y + v.z * v.z + v.w * v.w;
    float n = fmaxf(sqrtf(block_reduce_sum(ss)), 1e-7f);
    float nc = fminf(n, 10.0f);
    float f = sinhf(nc) / n;
    float4 w;
    w.x = v.x * f; w.y = v.y * f; w.z = v.z * f; w.w = v.w * f;
    if (threadIdx.x == 0) w.x = coshf(nc);
    orow[threadIdx.x] = w;
}

// ───────────────────────── mma.sync tf32 GEMM ─────────────────────────
// C[M,Nn] = A[M,K] @ B[Nn,K]^T + bias.  Inputs pre-rounded to tf32.
// CTA 128x128x32, 8 warps, warp tile 64x32. SMEM rows = 32 floats (128B),
// 16B-chunk XOR swizzle. 3-stage cp.async pipeline, 2 CTAs/SM (16 warps).

#define BM 128
#define BN 128
#define BK 32
#define NSTAGE 3
#define STAGE_BYTES (128 * 128)          // 128 rows x 128B
#define SMEM_TOTAL (2 * NSTAGE * STAGE_BYTES)   // 96 KB

__global__ __launch_bounds__(256, 2) void gemm_mma_tf32(const float* __restrict__ A,
                                                        const float* __restrict__ B,
                                                        const float* __restrict__ bias,
                                                        float* __restrict__ C,
                                                        int M, int Nn, int K) {
    extern __shared__ char smem[];
    const uint32_t sbase = smem_u32(smem);          // A stages
    const uint32_t sbase_b = sbase + NSTAGE * STAGE_BYTES;

    const int tid  = threadIdx.x;
    const int wid  = tid >> 5;
    const int lane = tid & 31;
    const int g    = lane >> 2;
    const int q    = lane & 3;

    const int bm = blockIdx.y * BM;
    const int bn = blockIdx.x * BN;
    const int wm = (wid & 1) * 64;
    const int wn = (wid >> 1) * 32;

    // ldmatrix lane-address precompute
    const int mat = lane >> 3, r8 = lane & 7;
    uint32_t a_rowoff[4], a_xor[4];
    const uint32_t a_chi = (uint32_t)(mat >> 1);
    #pragma unroll
    for (int mt = 0; mt < 4; mt++) {
        int row = wm + mt * 16 + (mat & 1) * 8 + r8;
        a_rowoff[mt] = (uint32_t)row * 128u;
        a_xor[mt] = (uint32_t)(row & 7);
    }
    uint32_t b_rowoff[2], b_xor[2];
    const uint32_t b_chi = (uint32_t)(mat & 1);
    #pragma unroll
    for (int np = 0; np < 2; np++) {
        int row = wn + np * 16 + (mat >> 1) * 8 + r8;
        b_rowoff[np] = (uint32_t)row * 128u;
        b_xor[np] = (uint32_t)(row & 7);
    }

    float acc[4][4][4];
    #pragma unroll
    for (int i = 0; i < 4; i++)
        #pragma unroll
        for (int j = 0; j < 4; j++)
            #pragma unroll
            for (int r = 0; r < 4; r++) acc[i][j][r] = 0.0f;

    const int NC = K / BK;

    auto load_stage = [&](int c, int s) {
        const float* Ab = A + (size_t)bm * K + (size_t)c * BK;
        const float* Bb = B + (size_t)bn * K + (size_t)c * BK;
        const uint32_t ad = sbase + (uint32_t)s * STAGE_BYTES;
        const uint32_t bd = sbase_b + (uint32_t)s * STAGE_BYTES;
        #pragma unroll
        for (int it = 0; it < 4; it++) {
            int slot = tid + it * 256;
            int r = slot >> 3, c4 = slot & 7;
            uint32_t sw = (uint32_t)(c4 ^ (r & 7)) << 4;
            CP_ASYNC16(ad + (uint32_t)r * 128u + sw, Ab + (size_t)r * K + c4 * 4);
        }
        #pragma unroll
        for (int it = 0; it < 4; it++) {
            int slot = tid + it * 256;
            int r = slot >> 3, c4 = slot & 7;
            uint32_t sw = (uint32_t)(c4 ^ (r & 7)) << 4;
            CP_ASYNC16(bd + (uint32_t)r * 128u + sw, Bb + (size_t)r * K + c4 * 4);
        }
    };

    // prologue: stages 0..1
    #pragma unroll
    for (int s = 0; s < NSTAGE - 1; s++) {
        if (s < NC) load_stage(s, s);
        CP_COMMIT();
    }

    int sc = 0;                       // compute stage
    int sl = NSTAGE - 1;              // next load stage
    for (int c = 0; c < NC; c++) {
        if (c + NSTAGE - 1 < NC) load_stage(c + NSTAGE - 1, sl);
        sl = (sl == NSTAGE - 1) ? 0 : sl + 1;
        CP_COMMIT();
        CP_WAIT2();
        __syncthreads();

        const uint32_t ast = sbase + (uint32_t)sc * STAGE_BYTES;
        const uint32_t bst = sbase_b + (uint32_t)sc * STAGE_BYTES;
        sc = (sc == NSTAGE - 1) ? 0 : sc + 1;

        #pragma unroll
        for (int ks = 0; ks < 4; ks++) {
            uint32_t af[4][4];
            #pragma unroll
            for (int mt = 0; mt < 4; mt++) {
                uint32_t addr = ast + a_rowoff[mt] +
                                ((((uint32_t)ks * 2u + a_chi) ^ a_xor[mt]) << 4);
                ldsm_x4(af[mt][0], af[mt][1], af[mt][2], af[mt][3], addr);
            }
            uint32_t bf[4][2];
            #pragma unroll
            for (int np = 0; np < 2; np++) {
                uint32_t addr = bst + b_rowoff[np] +
                                ((((uint32_t)ks * 2u + b_chi) ^ b_xor[np]) << 4);
                ldsm_x4(bf[2 * np][0], bf[2 * np][1], bf[2 * np + 1][0], bf[2 * np + 1][1], addr);
            }
            #pragma unroll
            for (int mt = 0; mt < 4; mt++)
                #pragma unroll
                for (int nt = 0; nt < 4; nt++)
                    mma_tf32(acc[mt][nt][0], acc[mt][nt][1], acc[mt][nt][2], acc[mt][nt][3],
                             af[mt][0], af[mt][1], af[mt][2], af[mt][3],
                             bf[nt][0], bf[nt][1]);
        }
        __syncthreads();
    }
    CP_WAIT0();

    // Epilogue
    #pragma unroll
    for (int mt = 0; mt < 4; mt++) {
        const int r0 = bm + wm + mt * 16 + g;
        #pragma unroll
        for (int nt = 0; nt < 4; nt++) {
            const int c0 = bn + wn + nt * 8 + q * 2;
            float2 bv = *reinterpret_cast<const float2*>(bias + c0);
            float2 o0, o1;
            o0.x = acc[mt][nt][0] + bv.x;
            o0.y = acc[mt][nt][1] + bv.y;
            o1.x = acc[mt][nt][2] + bv.x;
            o1.y = acc[mt][nt][3] + bv.y;
            *reinterpret_cast<float2*>(&C[(size_t)r0 * Nn + c0]) = o0;
            *reinterpret_cast<float2*>(&C[(size_t)(r0 + 8) * Nn + c0]) = o1;
        }
    }
}

// ───────────────────────── launch ─────────────────────────
extern "C" void kernel_launch(void* const* d_in, const int* in_sizes, int n_in,
                              void* d_out, int out_size) {
    const float* x  = (const float*)d_in[0];
    const float* W1 = (const float*)d_in[1];
    const float* b1 = (const float*)d_in[2];
    const float* W2 = (const float*)d_in[3];
    const float* b2 = (const float*)d_in[4];
    const float* W3 = (const float*)d_in[5];
    const float* b3 = (const float*)d_in[6];
    float* out = (float*)d_out;

    float *buf0, *buf1, *w1r, *w2r, *w3r;
    cudaGetSymbolAddress((void**)&buf0, g_buf0);
    cudaGetSymbolAddress((void**)&buf1, g_buf1);
    cudaGetSymbolAddress((void**)&w1r, g_w1r);
    cudaGetSymbolAddress((void**)&w2r, g_w2r);
    cudaGetSymbolAddress((void**)&w3r, g_w3r);

    cudaFuncSetAttribute(gemm_mma_tf32, cudaFuncAttributeMaxDynamicSharedMemorySize, SMEM_TOTAL);

    // Pre-round weights to tf32 (rna)
    round_tf32_kernel<<<(DHID * DIN / 4 + 255) / 256, 256>>>((const float4*)W1, (float4*)w1r, DHID * DIN / 4);
    round_tf32_kernel<<<(DHID * DHID / 4 + 255) / 256, 256>>>((const float4*)W2, (float4*)w2r, DHID * DHID / 4);
    round_tf32_kernel<<<(DOUT * DHID / 4 + 255) / 256, 256>>>((const float4*)W3, (float4*)w3r, DOUT * DHID / 4);

    // t1 = logmap0(x) (tf32-rounded)
    prep_kernel<<<NROWS, 256>>>(x, buf0);

    // y1 = t1 @ W1^T + b1
    {
        dim3 grid(DHID / BN, NROWS / BM);
        gemm_mma_tf32<<<grid, 256, SMEM_TOTAL>>>(buf0, w1r, b1, buf1, NROWS, DHID, DIN);
    }
    transform_kernel<<<NROWS, 256>>>(buf1, buf0, DHID);

    // y2 = t2 @ W2^T + b2
    {
        dim3 grid(DHID / BN, NROWS / BM);
        gemm_mma_tf32<<<grid, 256, SMEM_TOTAL>>>(buf0, w2r, b2, buf1, NROWS, DHID, DHID);
    }
    transform_kernel<<<NROWS, 256>>>(buf1, buf0, DHID);

    // y3 = t3 @ W3^T + b3
    {
        dim3 grid(DOUT / BN, NROWS / BM);
        gemm_mma_tf32<<<grid, 256, SMEM_TOTAL>>>(buf0, w3r, b3, buf1, NROWS, DOUT, DHID);
    }
    final_kernel<<<NROWS, 256>>>(buf1, out);
}

// round 12
// speedup vs baseline: 9.3914x; 1.8525x over previous
#include <cuda_runtime.h>
#include <cuda_fp16.h>
#include <math.h>
#include <cstdint>

#define NROWS 8192
#define DIN   1024
#define DHID  4096
#define DOUT  1024

// fp32 GEMM outputs
__device__ float g_buf0[NROWS * DHID];
// fp16 GEMM inputs (activations)
__device__ __half g_act[NROWS * DHID];
// fp16 weights
__device__ __half g_w1h[DHID * DIN];
__device__ __half g_w2h[DHID * DHID];
__device__ __half g_w3h[DOUT * DHID];

// ───────────────────────── low-level helpers ─────────────────────────
__device__ __forceinline__ uint32_t smem_u32(const void* p) {
    uint32_t a;
    asm("{ .reg .u64 t; cvta.to.shared.u64 t, %1; cvt.u32.u64 %0, t; }" : "=r"(a) : "l"(p));
    return a;
}
__device__ __forceinline__ void ldsm_x4(uint32_t& r0, uint32_t& r1, uint32_t& r2, uint32_t& r3,
                                        uint32_t addr) {
    asm volatile("ldmatrix.sync.aligned.m8n8.x4.shared.b16 {%0,%1,%2,%3}, [%4];"
                 : "=r"(r0), "=r"(r1), "=r"(r2), "=r"(r3) : "r"(addr));
}
__device__ __forceinline__ void mma_f16(float& d0, float& d1, float& d2, float& d3,
                                        uint32_t a0, uint32_t a1, uint32_t a2, uint32_t a3,
                                        uint32_t b0, uint32_t b1) {
    asm volatile(
        "mma.sync.aligned.m16n8k16.row.col.f32.f16.f16.f32 "
        "{%0,%1,%2,%3}, {%4,%5,%6,%7}, {%8,%9}, {%0,%1,%2,%3};"
        : "+f"(d0), "+f"(d1), "+f"(d2), "+f"(d3)
        : "r"(a0), "r"(a1), "r"(a2), "r"(a3), "r"(b0), "r"(b1));
}
#define CP_ASYNC16(dst, src) \
    asm volatile("cp.async.cg.shared.global [%0], [%1], 16;\n" :: "r"(dst), "l"(src))
#define CP_COMMIT()  asm volatile("cp.async.commit_group;\n" ::: "memory")
#define CP_WAIT2()   asm volatile("cp.async.wait_group 2;\n" ::: "memory")
#define CP_WAIT0()   asm volatile("cp.async.wait_group 0;\n" ::: "memory")

// ───────────────────────── elementwise kernels ─────────────────────────
__device__ __forceinline__ float block_reduce_sum(float v) {
    __shared__ float sh[33];
    int lane = threadIdx.x & 31;
    int wid  = threadIdx.x >> 5;
    #pragma unroll
    for (int o = 16; o > 0; o >>= 1) v += __shfl_down_sync(0xffffffffu, v, o);
    if (lane == 0) sh[wid] = v;
    __syncthreads();
    if (wid == 0) {
        float t = (lane < (int)(blockDim.x >> 5)) ? sh[lane] : 0.0f;
        #pragma unroll
        for (int o = 16; o > 0; o >>= 1) t += __shfl_down_sync(0xffffffffu, t, o);
        if (lane == 0) sh[32] = t;
    }
    __syncthreads();
    return sh[32];
}

__device__ __forceinline__ uint32_t pack_h2(float a, float b) {
    __half2 h = __floats2half2_rn(a, b);
    return *reinterpret_cast<uint32_t*>(&h);
}

// fp32 -> fp16 weight conversion: 4 floats in -> 2 half2 out
__global__ __launch_bounds__(256) void w2h_kernel(const float4* __restrict__ in,
                                                  uint2* __restrict__ out, int n4) {
    int i = blockIdx.x * blockDim.x + threadIdx.x;
    if (i < n4) {
        float4 v = in[i];
        uint2 o;
        o.x = pack_h2(v.x, v.y);
        o.y = pack_h2(v.z, v.w);
        out[i] = o;
    }
}

// t = logmap0(x) -> fp16 (GEMM input)
__global__ __launch_bounds__(256) void prep_kernel(const float* __restrict__ x,
                                                   __half* __restrict__ o) {
    int row = blockIdx.x;
    const float4* xr = reinterpret_cast<const float4*>(x + (size_t)row * DIN);
    uint2* orow = reinterpret_cast<uint2*>(o + (size_t)row * DIN);
    float4 v = xr[threadIdx.x];
    float ss;
    __shared__ float s_x0;
    if (threadIdx.x == 0) {
        s_x0 = v.x;
        ss = v.y * v.y + v.z * v.z + v.w * v.w;
    } else {
        ss = v.x * v.x + v.y * v.y + v.z * v.z + v.w * v.w;
    }
    float tot = block_reduce_sum(ss);
    float ns = fmaxf(sqrtf(tot), 1e-7f);
    float d = acoshf(fmaxf(s_x0, 1.0f + 1e-7f));
    float s = d / ns;
    float a0 = (threadIdx.x == 0) ? 0.0f : v.x * s;
    uint2 w;
    w.x = pack_h2(a0, v.y * s);
    w.y = pack_h2(v.z * s, v.w * s);
    orow[threadIdx.x] = w;
}

// inter-layer collapse: fp32 y -> fp16 next GEMM input
__global__ __launch_bounds__(256) void transform_kernel(const float* __restrict__ y,
                                                        __half* __restrict__ o, int D) {
    int row = blockIdx.x;
    const float4* yr = reinterpret_cast<const float4*>(y + (size_t)row * D);
    uint2* orow = reinterpret_cast<uint2*>(o + (size_t)row * D);
    int n4 = D >> 2;
    float ss = 0.0f;
    for (int i = threadIdx.x; i < n4; i += blockDim.x) {
        float4 v = yr[i];
        if (i == 0) ss += v.y * v.y + v.z * v.z + v.w * v.w;
        else        ss += v.x * v.x + v.y * v.y + v.z * v.z + v.w * v.w;
    }
    float n = fmaxf(sqrtf(block_reduce_sum(ss)), 1e-7f);
    float f = fminf(n, 10.0f) / n;
    for (int i = threadIdx.x; i < n4; i += blockDim.x) {
        float4 v = yr[i];
        float a0 = (i == 0) ? 0.0f : v.x * f;
        uint2 w;
        w.x = pack_h2(a0, v.y * f);
        w.y = pack_h2(v.z * f, v.w * f);
        orow[i] = w;
    }
}

__global__ __launch_bounds__(256) void final_kernel(const float* __restrict__ y,
                                                    float* __restrict__ o) {
    int row = blockIdx.x;
    const float4* yr = reinterpret_cast<const float4*>(y + (size_t)row * DOUT);
    float4* orow = reinterpret_cast<float4*>(o + (size_t)row * DOUT);
    float4 v = yr[threadIdx.x];
    float ss;
    if (threadIdx.x == 0) ss = v.y * v.y + v.z * v.z + v.w * v.w;
    else                  ss = v.x * v.x + v.y * v.y + v.z * v.z + v.w * v.w;
    float n = fmaxf(sqrtf(block_reduce_sum(ss)), 1e-7f);
    float nc = fminf(n, 10.0f);
    float f = sinhf(nc) / n;
    float4 w;
    w.x = v.x * f; w.y = v.y * f; w.z = v.z * f; w.w = v.w * f;
    if (threadIdx.x == 0) w.x = coshf(nc);
    orow[threadIdx.x] = w;
}

// ───────────────────────── mma.sync fp16 GEMM ─────────────────────────
// C[M,Nn] = A[M,K] @ B[Nn,K]^T + bias.  A,B fp16, C fp32.
// CTA 128x128x64(halves), 8 warps, warp tile 64x32 (m16n8k16).
// SMEM rows = 64 halves (128B), 16B-chunk XOR swizzle, 3-stage cp.async,
// 2 CTAs/SM.

#define BM 128
#define BN 128
#define BK 64
#define NSTAGE 3
#define STAGE_BYTES (128 * 128)          // 128 rows x 128B
#define SMEM_TOTAL (2 * NSTAGE * STAGE_BYTES)   // 96 KB

__global__ __launch_bounds__(256, 2) void gemm_mma_f16(const __half* __restrict__ A,
                                                       const __half* __restrict__ B,
                                                       const float* __restrict__ bias,
                                                       float* __restrict__ C,
                                                       int M, int Nn, int K) {
    extern __shared__ char smem[];
    const uint32_t sbase = smem_u32(smem);          // A stages
    const uint32_t sbase_b = sbase + NSTAGE * STAGE_BYTES;

    const int tid  = threadIdx.x;
    const int wid  = tid >> 5;
    const int lane = tid & 31;
    const int g    = lane >> 2;
    const int q    = lane & 3;

    const int bm = blockIdx.y * BM;
    const int bn = blockIdx.x * BN;
    const int wm = (wid & 1) * 64;
    const int wn = (wid >> 1) * 32;

    // ldmatrix lane-address precompute (16B chunks; identical geometry to tf32 version)
    const int mat = lane >> 3, r8 = lane & 7;
    uint32_t a_rowoff[4], a_xor[4];
    const uint32_t a_chi = (uint32_t)(mat >> 1);
    #pragma unroll
    for (int mt = 0; mt < 4; mt++) {
        int row = wm + mt * 16 + (mat & 1) * 8 + r8;
        a_rowoff[mt] = (uint32_t)row * 128u;
        a_xor[mt] = (uint32_t)(row & 7);
    }
    uint32_t b_rowoff[2], b_xor[2];
    const uint32_t b_chi = (uint32_t)(mat & 1);
    #pragma unroll
    for (int np = 0; np < 2; np++) {
        int row = wn + np * 16 + (mat >> 1) * 8 + r8;
        b_rowoff[np] = (uint32_t)row * 128u;
        b_xor[np] = (uint32_t)(row & 7);
    }

    float acc[4][4][4];
    #pragma unroll
    for (int i = 0; i < 4; i++)
        #pragma unroll
        for (int j = 0; j < 4; j++)
            #pragma unroll
            for (int r = 0; r < 4; r++) acc[i][j][r] = 0.0f;

    const int NC = K / BK;

    auto load_stage = [&](int c, int s) {
        const __half* Ab = A + (size_t)bm * K + (size_t)c * BK;
        const __half* Bb = B + (size_t)bn * K + (size_t)c * BK;
        const uint32_t ad = sbase + (uint32_t)s * STAGE_BYTES;
        const uint32_t bd = sbase_b + (uint32_t)s * STAGE_BYTES;
        #pragma unroll
        for (int it = 0; it < 4; it++) {
            int slot = tid + it * 256;
            int r = slot >> 3, c4 = slot & 7;
            uint32_t sw = (uint32_t)(c4 ^ (r & 7)) << 4;
            CP_ASYNC16(ad + (uint32_t)r * 128u + sw, Ab + (size_t)r * K + c4 * 8);
        }
        #pragma unroll
        for (int it = 0; it < 4; it++) {
            int slot = tid + it * 256;
            int r = slot >> 3, c4 = slot & 7;
            uint32_t sw = (uint32_t)(c4 ^ (r & 7)) << 4;
            CP_ASYNC16(bd + (uint32_t)r * 128u + sw, Bb + (size_t)r * K + c4 * 8);
        }
    };

    // prologue
    #pragma unroll
    for (int s = 0; s < NSTAGE - 1; s++) {
        if (s < NC) load_stage(s, s);
        CP_COMMIT();
    }

    int sc = 0;
    int sl = NSTAGE - 1;
    for (int c = 0; c < NC; c++) {
        if (c + NSTAGE - 1 < NC) load_stage(c + NSTAGE - 1, sl);
        sl = (sl == NSTAGE - 1) ? 0 : sl + 1;
        CP_COMMIT();
        CP_WAIT2();
        __syncthreads();

        const uint32_t ast = sbase + (uint32_t)sc * STAGE_BYTES;
        const uint32_t bst = sbase_b + (uint32_t)sc * STAGE_BYTES;
        sc = (sc == NSTAGE - 1) ? 0 : sc + 1;

        #pragma unroll
        for (int ks = 0; ks < 4; ks++) {   // 4 x k16 = BK 64 halves
            uint32_t af[4][4];
            #pragma unroll
            for (int mt = 0; mt < 4; mt++) {
                uint32_t addr = ast + a_rowoff[mt] +
                                ((((uint32_t)ks * 2u + a_chi) ^ a_xor[mt]) << 4);
                ldsm_x4(af[mt][0], af[mt][1], af[mt][2], af[mt][3], addr);
            }
            uint32_t bf[4][2];
            #pragma unroll
            for (int np = 0; np < 2; np++) {
                uint32_t addr = bst + b_rowoff[np] +
                                ((((uint32_t)ks * 2u + b_chi) ^ b_xor[np]) << 4);
                ldsm_x4(bf[2 * np][0], bf[2 * np][1], bf[2 * np + 1][0], bf[2 * np + 1][1], addr);
            }
            #pragma unroll
            for (int mt = 0; mt < 4; mt++)
                #pragma unroll
                for (int nt = 0; nt < 4; nt++)
                    mma_f16(acc[mt][nt][0], acc[mt][nt][1], acc[mt][nt][2], acc[mt][nt][3],
                            af[mt][0], af[mt][1], af[mt][2], af[mt][3],
                            bf[nt][0], bf[nt][1]);
        }
        __syncthreads();
    }
    CP_WAIT0();

    // Epilogue
    #pragma unroll
    for (int mt = 0; mt < 4; mt++) {
        const int r0 = bm + wm + mt * 16 + g;
        #pragma unroll
        for (int nt = 0; nt < 4; nt++) {
            const int c0 = bn + wn + nt * 8 + q * 2;
            float2 bv = *reinterpret_cast<const float2*>(bias + c0);
            float2 o0, o1;
            o0.x = acc[mt][nt][0] + bv.x;
            o0.y = acc[mt][nt][1] + bv.y;
            o1.x = acc[mt][nt][2] + bv.x;
            o1.y = acc[mt][nt][3] + bv.y;
            *reinterpret_cast<float2*>(&C[(size_t)r0 * Nn + c0]) = o0;
            *reinterpret_cast<float2*>(&C[(size_t)(r0 + 8) * Nn + c0]) = o1;
        }
    }
}

// ───────────────────────── launch ─────────────────────────
extern "C" void kernel_launch(void* const* d_in, const int* in_sizes, int n_in,
                              void* d_out, int out_size) {
    const float* x  = (const float*)d_in[0];
    const float* W1 = (const float*)d_in[1];
    const float* b1 = (const float*)d_in[2];
    const float* W2 = (const float*)d_in[3];
    const float* b2 = (const float*)d_in[4];
    const float* W3 = (const float*)d_in[5];
    const float* b3 = (const float*)d_in[6];
    float* out = (float*)d_out;

    float* buf0;
    __half *act, *w1h, *w2h, *w3h;
    cudaGetSymbolAddress((void**)&buf0, g_buf0);
    cudaGetSymbolAddress((void**)&act, g_act);
    cudaGetSymbolAddress((void**)&w1h, g_w1h);
    cudaGetSymbolAddress((void**)&w2h, g_w2h);
    cudaGetSymbolAddress((void**)&w3h, g_w3h);

    cudaFuncSetAttribute(gemm_mma_f16, cudaFuncAttributeMaxDynamicSharedMemorySize, SMEM_TOTAL);

    // fp16 weight conversion
    w2h_kernel<<<(DHID * DIN / 4 + 255) / 256, 256>>>((const float4*)W1, (uint2*)w1h, DHID * DIN / 4);
    w2h_kernel<<<(DHID * DHID / 4 + 255) / 256, 256>>>((const float4*)W2, (uint2*)w2h, DHID * DHID / 4);
    w2h_kernel<<<(DOUT * DHID / 4 + 255) / 256, 256>>>((const float4*)W3, (uint2*)w3h, DOUT * DHID / 4);

    // t1 = logmap0(x) -> fp16
    prep_kernel<<<NROWS, 256>>>(x, act);

    // y1 = t1 @ W1^T + b1
    {
        dim3 grid(DHID / BN, NROWS / BM);
        gemm_mma_f16<<<grid, 256, SMEM_TOTAL>>>(act, w1h, b1, buf0, NROWS, DHID, DIN);
    }
    transform_kernel<<<NROWS, 256>>>(buf0, act, DHID);

    // y2 = t2 @ W2^T + b2
    {
        dim3 grid(DHID / BN, NROWS / BM);
        gemm_mma_f16<<<grid, 256, SMEM_TOTAL>>>(act, w2h, b2, buf0, NROWS, DHID, DHID);
    }
    transform_kernel<<<NROWS, 256>>>(buf0, act, DHID);

    // y3 = t3 @ W3^T + b3
    {
        dim3 grid(DOUT / BN, NROWS / BM);
        gemm_mma_f16<<<grid, 256, SMEM_TOTAL>>>(act, w3h, b3, buf0, NROWS, DOUT, DHID);
    }
    final_kernel<<<NROWS, 256>>>(buf0, out);
}

// round 14
// speedup vs baseline: 9.7156x; 1.0345x over previous
#include <cuda_runtime.h>
#include <cuda_fp16.h>
#include <math.h>
#include <cstdint>

#define NROWS 8192
#define DIN   1024
#define DHID  4096
#define DOUT  1024

// half ping-pong activation buffers
__device__ __half g_h0[NROWS * DHID];
__device__ __half g_h1[NROWS * DHID];
// fp32 final GEMM output
__device__ float g_y3[NROWS * DOUT];
// fp16 weights
__device__ __half g_w1h[DHID * DIN];
__device__ __half g_w2h[DHID * DHID];
__device__ __half g_w3h[DOUT * DHID];

// ───────────────────────── low-level helpers ─────────────────────────
__device__ __forceinline__ uint32_t smem_u32(const void* p) {
    uint32_t a;
    asm("{ .reg .u64 t; cvta.to.shared.u64 t, %1; cvt.u32.u64 %0, t; }" : "=r"(a) : "l"(p));
    return a;
}
__device__ __forceinline__ void ldsm_x4(uint32_t& r0, uint32_t& r1, uint32_t& r2, uint32_t& r3,
                                        uint32_t addr) {
    asm volatile("ldmatrix.sync.aligned.m8n8.x4.shared.b16 {%0,%1,%2,%3}, [%4];"
                 : "=r"(r0), "=r"(r1), "=r"(r2), "=r"(r3) : "r"(addr));
}
__device__ __forceinline__ void mma_f16(float& d0, float& d1, float& d2, float& d3,
                                        uint32_t a0, uint32_t a1, uint32_t a2, uint32_t a3,
                                        uint32_t b0, uint32_t b1) {
    asm volatile(
        "mma.sync.aligned.m16n8k16.row.col.f32.f16.f16.f32 "
        "{%0,%1,%2,%3}, {%4,%5,%6,%7}, {%8,%9}, {%0,%1,%2,%3};"
        : "+f"(d0), "+f"(d1), "+f"(d2), "+f"(d3)
        : "r"(a0), "r"(a1), "r"(a2), "r"(a3), "r"(b0), "r"(b1));
}
#define CP_ASYNC16(dst, src) \
    asm volatile("cp.async.cg.shared.global [%0], [%1], 16;\n" :: "r"(dst), "l"(src))
#define CP_COMMIT()  asm volatile("cp.async.commit_group;\n" ::: "memory")
#define CP_WAIT1()   asm volatile("cp.async.wait_group 1;\n" ::: "memory")
#define CP_WAIT0()   asm volatile("cp.async.wait_group 0;\n" ::: "memory")

__device__ __forceinline__ uint32_t pack_h2(float a, float b) {
    __half2 h = __floats2half2_rn(a, b);
    return *reinterpret_cast<uint32_t*>(&h);
}

// ───────────────────────── elementwise kernels ─────────────────────────
__device__ __forceinline__ float block_reduce_sum(float v) {
    __shared__ float sh[33];
    int lane = threadIdx.x & 31;
    int wid  = threadIdx.x >> 5;
    #pragma unroll
    for (int o = 16; o > 0; o >>= 1) v += __shfl_down_sync(0xffffffffu, v, o);
    if (lane == 0) sh[wid] = v;
    __syncthreads();
    if (wid == 0) {
        float t = (lane < (int)(blockDim.x >> 5)) ? sh[lane] : 0.0f;
        #pragma unroll
        for (int o = 16; o > 0; o >>= 1) t += __shfl_down_sync(0xffffffffu, t, o);
        if (lane == 0) sh[32] = t;
    }
    __syncthreads();
    return sh[32];
}

// fp32 -> fp16 weight conversion
__global__ __launch_bounds__(256) void w2h_kernel(const float4* __restrict__ in,
                                                  uint2* __restrict__ out, int n4) {
    int i = blockIdx.x * blockDim.x + threadIdx.x;
    if (i < n4) {
        float4 v = in[i];
        uint2 o;
        o.x = pack_h2(v.x, v.y);
        o.y = pack_h2(v.z, v.w);
        out[i] = o;
    }
}

// t = logmap0(x) -> fp16
__global__ __launch_bounds__(256) void prep_kernel(const float* __restrict__ x,
                                                   __half* __restrict__ o) {
    int row = blockIdx.x;
    const float4* xr = reinterpret_cast<const float4*>(x + (size_t)row * DIN);
    uint2* orow = reinterpret_cast<uint2*>(o + (size_t)row * DIN);
    float4 v = xr[threadIdx.x];
    float ss;
    __shared__ float s_x0;
    if (threadIdx.x == 0) {
        s_x0 = v.x;
        ss = v.y * v.y + v.z * v.z + v.w * v.w;
    } else {
        ss = v.x * v.x + v.y * v.y + v.z * v.z + v.w * v.w;
    }
    float tot = block_reduce_sum(ss);
    float ns = fmaxf(sqrtf(tot), 1e-7f);
    float d = acoshf(fmaxf(s_x0, 1.0f + 1e-7f));
    float s = d / ns;
    float a0 = (threadIdx.x == 0) ? 0.0f : v.x * s;
    uint2 w;
    w.x = pack_h2(a0, v.y * s);
    w.y = pack_h2(v.z * s, v.w * s);
    orow[threadIdx.x] = w;
}

// In-place inter-layer collapse on fp16 y (D = DHID = 4096 fixed).
// Row held in registers (16 values/thread) across the reduction.
__global__ __launch_bounds__(256) void transform_h(__half* __restrict__ y) {
    int row = blockIdx.x;
    float4* yr = reinterpret_cast<float4*>(y + (size_t)row * DHID);
    float vals[16];
    float ss = 0.0f;
    #pragma unroll
    for (int it = 0; it < 2; it++) {
        float4 raw = yr[threadIdx.x + it * 256];
        const __half2* hp = reinterpret_cast<const __half2*>(&raw);
        #pragma unroll
        for (int j = 0; j < 4; j++) {
            float2 f = __half22float2(hp[j]);
            vals[it * 8 + 2 * j] = f.x;
            vals[it * 8 + 2 * j + 1] = f.y;
        }
    }
    #pragma unroll
    for (int e = 0; e < 16; e++) ss += vals[e] * vals[e];
    if (threadIdx.x == 0) ss -= vals[0] * vals[0];   // exclude time component
    float n = fmaxf(sqrtf(block_reduce_sum(ss)), 1e-7f);
    float f = fminf(n, 10.0f) / n;
    if (threadIdx.x == 0) vals[0] = 0.0f;
    #pragma unroll
    for (int it = 0; it < 2; it++) {
        float4 raw;
        uint32_t* up = reinterpret_cast<uint32_t*>(&raw);
        #pragma unroll
        for (int j = 0; j < 4; j++)
            up[j] = pack_h2(vals[it * 8 + 2 * j] * f, vals[it * 8 + 2 * j + 1] * f);
        yr[threadIdx.x + it * 256] = raw;
    }
}

__global__ __launch_bounds__(256) void final_kernel(const float* __restrict__ y,
                                                    float* __restrict__ o) {
    int row = blockIdx.x;
    const float4* yr = reinterpret_cast<const float4*>(y + (size_t)row * DOUT);
    float4* orow = reinterpret_cast<float4*>(o + (size_t)row * DOUT);
    float4 v = yr[threadIdx.x];
    float ss;
    if (threadIdx.x == 0) ss = v.y * v.y + v.z * v.z + v.w * v.w;
    else                  ss = v.x * v.x + v.y * v.y + v.z * v.z + v.w * v.w;
    float n = fmaxf(sqrtf(block_reduce_sum(ss)), 1e-7f);
    float nc = fminf(n, 10.0f);
    float f = sinhf(nc) / n;
    float4 w;
    w.x = v.x * f; w.y = v.y * f; w.z = v.z * f; w.w = v.w * f;
    if (threadIdx.x == 0) w.x = coshf(nc);
    orow[threadIdx.x] = w;
}

// ───────────────────────── mma.sync fp16 GEMM ─────────────────────────
// C[M,Nn] = A[M,K] @ B[Nn,K]^T + bias.  A,B fp16, C fp32 or fp16 (OutT).
// CTA 128x128x64, 8 warps, warp tile 64x32 (m16n8k16), 3-stage cp.async,
// ONE __syncthreads per mainloop iteration, 2 CTAs/SM.

#define BM 128
#define BN 128
#define BK 64
#define NSTAGE 3
#define STAGE_BYTES (128 * 128)
#define SMEM_TOTAL (2 * NSTAGE * STAGE_BYTES)   // 96 KB

template <typename OutT>
__global__ __launch_bounds__(256, 2) void gemm_mma_f16(const __half* __restrict__ A,
                                                       const __half* __restrict__ B,
                                                       const float* __restrict__ bias,
                                                       OutT* __restrict__ C,
                                                       int M, int Nn, int K) {
    extern __shared__ char smem[];
    const uint32_t sbase = smem_u32(smem);
    const uint32_t sbase_b = sbase + NSTAGE * STAGE_BYTES;

    const int tid  = threadIdx.x;
    const int wid  = tid >> 5;
    const int lane = tid & 31;
    const int g    = lane >> 2;
    const int q    = lane & 3;

    const int bm = blockIdx.y * BM;
    const int bn = blockIdx.x * BN;
    const int wm = (wid & 1) * 64;
    const int wn = (wid >> 1) * 32;

    const int mat = lane >> 3, r8 = lane & 7;
    uint32_t a_rowoff[4], a_xor[4];
    const uint32_t a_chi = (uint32_t)(mat >> 1);
    #pragma unroll
    for (int mt = 0; mt < 4; mt++) {
        int row = wm + mt * 16 + (mat & 1) * 8 + r8;
        a_rowoff[mt] = (uint32_t)row * 128u;
        a_xor[mt] = (uint32_t)(row & 7);
    }
    uint32_t b_rowoff[2], b_xor[2];
    const uint32_t b_chi = (uint32_t)(mat & 1);
    #pragma unroll
    for (int np = 0; np < 2; np++) {
        int row = wn + np * 16 + (mat >> 1) * 8 + r8;
        b_rowoff[np] = (uint32_t)row * 128u;
        b_xor[np] = (uint32_t)(row & 7);
    }

    float acc[4][4][4];
    #pragma unroll
    for (int i = 0; i < 4; i++)
        #pragma unroll
        for (int j = 0; j < 4; j++)
            #pragma unroll
            for (int r = 0; r < 4; r++) acc[i][j][r] = 0.0f;

    const int NC = K / BK;

    auto load_stage = [&](int c, int s) {
        const __half* Ab = A + (size_t)bm * K + (size_t)c * BK;
        const __half* Bb = B + (size_t)bn * K + (size_t)c * BK;
        const uint32_t ad = sbase + (uint32_t)s * STAGE_BYTES;
        const uint32_t bd = sbase_b + (uint32_t)s * STAGE_BYTES;
        #pragma unroll
        for (int it = 0; it < 4; it++) {
            int slot = tid + it * 256;
            int r = slot >> 3, c4 = slot & 7;
            uint32_t sw = (uint32_t)(c4 ^ (r & 7)) << 4;
            CP_ASYNC16(ad + (uint32_t)r * 128u + sw, Ab + (size_t)r * K + c4 * 8);
        }
        #pragma unroll
        for (int it = 0; it < 4; it++) {
            int slot = tid + it * 256;
            int r = slot >> 3, c4 = slot & 7;
            uint32_t sw = (uint32_t)(c4 ^ (r & 7)) << 4;
            CP_ASYNC16(bd + (uint32_t)r * 128u + sw, Bb + (size_t)r * K + c4 * 8);
        }
    };

    // prologue: stages 0,1 (NC >= 16 always here)
    load_stage(0, 0);
    CP_COMMIT();
    load_stage(1, 1);
    CP_COMMIT();

    int sc = 0, sl = 2;
    for (int c = 0; c < NC; c++) {
        CP_WAIT1();            // stage c landed
        __syncthreads();       // all warps done computing stage consumed at c-1
        if (c + 2 < NC) load_stage(c + 2, sl);
        CP_COMMIT();           // always commit (keeps group arithmetic uniform)
        sl = (sl == NSTAGE - 1) ? 0 : sl + 1;

        const uint32_t ast = sbase + (uint32_t)sc * STAGE_BYTES;
        const uint32_t bst = sbase_b + (uint32_t)sc * STAGE_BYTES;
        sc = (sc == NSTAGE - 1) ? 0 : sc + 1;

        #pragma unroll
        for (int ks = 0; ks < 4; ks++) {
            uint32_t af[4][4];
            #pragma unroll
            for (int mt = 0; mt < 4; mt++) {
                uint32_t addr = ast + a_rowoff[mt] +
                                ((((uint32_t)ks * 2u + a_chi) ^ a_xor[mt]) << 4);
                ldsm_x4(af[mt][0], af[mt][1], af[mt][2], af[mt][3], addr);
            }
            uint32_t bf[4][2];
            #pragma unroll
            for (int np = 0; np < 2; np++) {
                uint32_t addr = bst + b_rowoff[np] +
                                ((((uint32_t)ks * 2u + b_chi) ^ b_xor[np]) << 4);
                ldsm_x4(bf[2 * np][0], bf[2 * np][1], bf[2 * np + 1][0], bf[2 * np + 1][1], addr);
            }
            #pragma unroll
            for (int mt = 0; mt < 4; mt++)
                #pragma unroll
                for (int nt = 0; nt < 4; nt++)
                    mma_f16(acc[mt][nt][0], acc[mt][nt][1], acc[mt][nt][2], acc[mt][nt][3],
                            af[mt][0], af[mt][1], af[mt][2], af[mt][3],
                            bf[nt][0], bf[nt][1]);
        }
    }
    CP_WAIT0();

    // Epilogue
    #pragma unroll
    for (int mt = 0; mt < 4; mt++) {
        const int r0 = bm + wm + mt * 16 + g;
        #pragma unroll
        for (int nt = 0; nt < 4; nt++) {
            const int c0 = bn + wn + nt * 8 + q * 2;
            float2 bv = *reinterpret_cast<const float2*>(bias + c0);
            float v0 = acc[mt][nt][0] + bv.x;
            float v1 = acc[mt][nt][1] + bv.y;
            float v2 = acc[mt][nt][2] + bv.x;
            float v3 = acc[mt][nt][3] + bv.y;
            if constexpr (sizeof(OutT) == 2) {
                *reinterpret_cast<uint32_t*>(&C[(size_t)r0 * Nn + c0]) = pack_h2(v0, v1);
                *reinterpret_cast<uint32_t*>(&C[(size_t)(r0 + 8) * Nn + c0]) = pack_h2(v2, v3);
            } else {
                float2 o0{v0, v1}, o1{v2, v3};
                *reinterpret_cast<float2*>(&C[(size_t)r0 * Nn + c0]) = o0;
                *reinterpret_cast<float2*>(&C[(size_t)(r0 + 8) * Nn + c0]) = o1;
            }
        }
    }
}

// ───────────────────────── launch ─────────────────────────
extern "C" void kernel_launch(void* const* d_in, const int* in_sizes, int n_in,
                              void* d_out, int out_size) {
    const float* x  = (const float*)d_in[0];
    const float* W1 = (const float*)d_in[1];
    const float* b1 = (const float*)d_in[2];
    const float* W2 = (const float*)d_in[3];
    const float* b2 = (const float*)d_in[4];
    const float* W3 = (const float*)d_in[5];
    const float* b3 = (const float*)d_in[6];
    float* out = (float*)d_out;

    __half *h0, *h1, *w1h, *w2h, *w3h;
    float* y3;
    cudaGetSymbolAddress((void**)&h0, g_h0);
    cudaGetSymbolAddress((void**)&h1, g_h1);
    cudaGetSymbolAddress((void**)&y3, g_y3);
    cudaGetSymbolAddress((void**)&w1h, g_w1h);
    cudaGetSymbolAddress((void**)&w2h, g_w2h);
    cudaGetSymbolAddress((void**)&w3h, g_w3h);

    cudaFuncSetAttribute(gemm_mma_f16<__half>, cudaFuncAttributeMaxDynamicSharedMemorySize, SMEM_TOTAL);
    cudaFuncSetAttribute(gemm_mma_f16<float>, cudaFuncAttributeMaxDynamicSharedMemorySize, SMEM_TOTAL);

    // fp16 weight conversion
    w2h_kernel<<<(DHID * DIN / 4 + 255) / 256, 256>>>((const float4*)W1, (uint2*)w1h, DHID * DIN / 4);
    w2h_kernel<<<(DHID * DHID / 4 + 255) / 256, 256>>>((const float4*)W2, (uint2*)w2h, DHID * DHID / 4);
    w2h_kernel<<<(DOUT * DHID / 4 + 255) / 256, 256>>>((const float4*)W3, (uint2*)w3h, DOUT * DHID / 4);

    // t1 = logmap0(x) -> fp16 h0
    prep_kernel<<<NROWS, 256>>>(x, h0);

    // y1 = t1 @ W1^T + b1 -> fp16 h1
    {
        dim3 grid(DHID / BN, NROWS / BM);
        gemm_mma_f16<__half><<<grid, 256, SMEM_TOTAL>>>(h0, w1h, b1, h1, NROWS, DHID, DIN);
    }
    transform_h<<<NROWS, 256>>>(h1);   // in place

    // y2 = t2 @ W2^T + b2 -> fp16 h0
    {
        dim3 grid(DHID / BN, NROWS / BM);
        gemm_mma_f16<__half><<<grid, 256, SMEM_TOTAL>>>(h1, w2h, b2, h0, NROWS, DHID, DHID);
    }
    transform_h<<<NROWS, 256>>>(h0);   // in place

    // y3 = t3 @ W3^T + b3 -> fp32
    {
        dim3 grid(DOUT / BN, NROWS / BM);
        gemm_mma_f16<float><<<grid, 256, SMEM_TOTAL>>>(h0, w3h, b3, y3, NROWS, DOUT, DHID);
    }
    final_kernel<<<NROWS, 256>>>(y3, out);
}